// round 1
// baseline (speedup 1.0000x reference)
#include <cuda_runtime.h>
#include <math.h>

#define LQ   1024
#define BZ   8
#define DD   512
#define NH   8
#define DH   64
#define MTOT (BZ*LQ)   // 8192

// Scratch (allocation-free rule: device globals)
__device__ float g_Q[BZ*LQ*DD];
__device__ float g_K[BZ*LQ*DD];
__device__ float g_V[BZ*LQ*DD];
__device__ float g_invn[BZ*LQ];
__device__ unsigned char g_mask[(size_t)BZ*LQ*LQ];

// ---------------------------------------------------------------------------
// Kernel 1: per-row inverse norms of h (h[b,i,:] = query[i,b,:])
// ---------------------------------------------------------------------------
__global__ void __launch_bounds__(256) norms_kernel(const float* __restrict__ query)
{
    int m    = blockIdx.x * 8 + (threadIdx.x >> 5);   // row id = b*1024+i
    int lane = threadIdx.x & 31;
    int b = m >> 10, i = m & 1023;
    const float* p = query + (size_t)i * (BZ*DD) + (size_t)b * DD;
    float ss = 0.f;
    #pragma unroll
    for (int j = 0; j < 16; ++j) {
        float v = p[lane + j*32];
        ss += v * v;
    }
    #pragma unroll
    for (int o = 16; o > 0; o >>= 1) ss += __shfl_xor_sync(0xffffffffu, ss, o);
    if (lane == 0) g_invn[m] = 1.f / fmaxf(sqrtf(ss), 1e-8f);
}

// ---------------------------------------------------------------------------
// Kernel 2: QKV projections.  C[m,n] = sum_k h[m,k]*W[n,k] + bias[n]
// 128x128 tile, BK=16, 256 threads, 8x8 micro (split 4+4 to avoid conflicts)
// blockIdx.z selects (Wq,bq,g_Q) / (Wk,bk,g_K) / (Wv,bv,g_V)
// ---------------------------------------------------------------------------
__global__ void __launch_bounds__(256) qkv_kernel(
    const float* __restrict__ query,
    const float* __restrict__ Wq, const float* __restrict__ bq,
    const float* __restrict__ Wk, const float* __restrict__ bk,
    const float* __restrict__ Wv, const float* __restrict__ bv)
{
    const float* W; const float* bias; float* out;
    if      (blockIdx.z == 0) { W = Wq; bias = bq; out = g_Q; }
    else if (blockIdx.z == 1) { W = Wk; bias = bk; out = g_K; }
    else                      { W = Wv; bias = bv; out = g_V; }

    __shared__ float As[16][128];   // [k][m]
    __shared__ float Bs[16][128];   // [k][n]

    int tid = threadIdx.x;
    int tx = tid & 15, ty = tid >> 4;
    int m0 = blockIdx.y * 128, n0 = blockIdx.x * 128;

    float acc[8][8];
    #pragma unroll
    for (int i = 0; i < 8; ++i)
        #pragma unroll
        for (int j = 0; j < 8; ++j) acc[i][j] = 0.f;

    for (int kt = 0; kt < DD/16; ++kt) {
        int k0 = kt * 16;
        #pragma unroll
        for (int q = 0; q < 2; ++q) {
            int f   = tid + q*256;
            int row = f >> 2;
            int kk  = (f & 3) << 2;
            int m = m0 + row; int b = m >> 10; int i = m & 1023;
            float4 va = *(const float4*)(query + (size_t)i*(BZ*DD) + (size_t)b*DD + k0 + kk);
            As[kk+0][row] = va.x; As[kk+1][row] = va.y;
            As[kk+2][row] = va.z; As[kk+3][row] = va.w;
            int n = n0 + row;
            float4 vb = *(const float4*)(W + (size_t)n*DD + k0 + kk);
            Bs[kk+0][row] = vb.x; Bs[kk+1][row] = vb.y;
            Bs[kk+2][row] = vb.z; Bs[kk+3][row] = vb.w;
        }
        __syncthreads();
        #pragma unroll
        for (int k = 0; k < 16; ++k) {
            float a[8], bb[8];
            *(float4*)(a)    = *(const float4*)&As[k][ty*4];
            *(float4*)(a+4)  = *(const float4*)&As[k][64 + ty*4];
            *(float4*)(bb)   = *(const float4*)&Bs[k][tx*4];
            *(float4*)(bb+4) = *(const float4*)&Bs[k][64 + tx*4];
            #pragma unroll
            for (int i = 0; i < 8; ++i)
                #pragma unroll
                for (int j = 0; j < 8; ++j) acc[i][j] += a[i] * bb[j];
        }
        __syncthreads();
    }
    // epilogue: + bias, store
    #pragma unroll
    for (int i = 0; i < 8; ++i) {
        int r = (i < 4) ? (ty*4 + i) : (64 + ty*4 + (i-4));
        int m = m0 + r;
        #pragma unroll
        for (int jh = 0; jh < 2; ++jh) {
            int c = (jh == 0) ? (tx*4) : (64 + tx*4);
            float4 bv4 = *(const float4*)(bias + n0 + c);
            float4 o;
            o.x = acc[i][jh*4+0] + bv4.x;
            o.y = acc[i][jh*4+1] + bv4.y;
            o.z = acc[i][jh*4+2] + bv4.z;
            o.w = acc[i][jh*4+3] + bv4.w;
            *(float4*)(out + (size_t)m*DD + n0 + c) = o;
        }
    }
}

// ---------------------------------------------------------------------------
// Kernel 3: cos GEMM (h·hT) fused with IoU + thresholds -> byte mask
// mask[b,i,j] = ((iou>0.2 && i!=j) || cos<=0.2)
// ---------------------------------------------------------------------------
__global__ void __launch_bounds__(256) mask_kernel(
    const float* __restrict__ query, const float* __restrict__ segments)
{
    int b = blockIdx.z;
    __shared__ float As[16][128];
    __shared__ float Bs[16][128];

    int tid = threadIdx.x;
    int tx = tid & 15, ty = tid >> 4;
    int i0 = blockIdx.y * 128, j0 = blockIdx.x * 128;

    float acc[8][8];
    #pragma unroll
    for (int i = 0; i < 8; ++i)
        #pragma unroll
        for (int j = 0; j < 8; ++j) acc[i][j] = 0.f;

    const float* qb = query + (size_t)b * DD;   // + row*(BZ*DD)

    for (int kt = 0; kt < DD/16; ++kt) {
        int k0 = kt * 16;
        #pragma unroll
        for (int q = 0; q < 2; ++q) {
            int f   = tid + q*256;
            int row = f >> 2;
            int kk  = (f & 3) << 2;
            float4 va = *(const float4*)(qb + (size_t)(i0+row)*(BZ*DD) + k0 + kk);
            As[kk+0][row] = va.x; As[kk+1][row] = va.y;
            As[kk+2][row] = va.z; As[kk+3][row] = va.w;
            float4 vb = *(const float4*)(qb + (size_t)(j0+row)*(BZ*DD) + k0 + kk);
            Bs[kk+0][row] = vb.x; Bs[kk+1][row] = vb.y;
            Bs[kk+2][row] = vb.z; Bs[kk+3][row] = vb.w;
        }
        __syncthreads();
        #pragma unroll
        for (int k = 0; k < 16; ++k) {
            float a[8], bb[8];
            *(float4*)(a)    = *(const float4*)&As[k][ty*4];
            *(float4*)(a+4)  = *(const float4*)&As[k][64 + ty*4];
            *(float4*)(bb)   = *(const float4*)&Bs[k][tx*4];
            *(float4*)(bb+4) = *(const float4*)&Bs[k][64 + tx*4];
            #pragma unroll
            for (int i = 0; i < 8; ++i)
                #pragma unroll
                for (int j = 0; j < 8; ++j) acc[i][j] += a[i] * bb[j];
        }
        __syncthreads();
    }

    // epilogue: cos + iou + thresholds
    const float* seg = segments + (size_t)b * LQ * 2;
    float ni[8], si[8], ei[8], li[8];
    float nj[8], sj[8], ej[8], lj[8];
    int   ri[8], rj[8];
    #pragma unroll
    for (int i = 0; i < 8; ++i) {
        int r = (i < 4) ? (ty*4 + i) : (64 + ty*4 + (i-4));
        int gi = i0 + r;
        ri[i] = gi;
        ni[i] = g_invn[b*LQ + gi];
        float cc = seg[gi*2], ll = seg[gi*2+1];
        si[i] = cc - ll*0.5f; ei[i] = cc + ll*0.5f; li[i] = ll;
    }
    #pragma unroll
    for (int j = 0; j < 8; ++j) {
        int c = (j < 4) ? (tx*4 + j) : (64 + tx*4 + (j-4));
        int gj = j0 + c;
        rj[j] = gj;
        nj[j] = g_invn[b*LQ + gj];
        float cc = seg[gj*2], ll = seg[gj*2+1];
        sj[j] = cc - ll*0.5f; ej[j] = cc + ll*0.5f; lj[j] = ll;
    }
    unsigned char* mb = g_mask + ((size_t)b << 20);
    #pragma unroll
    for (int i = 0; i < 8; ++i) {
        #pragma unroll
        for (int j = 0; j < 8; ++j) {
            float cosv  = acc[i][j] * ni[i] * nj[j];
            float inter = fmaxf(fminf(ei[i], ej[j]) - fmaxf(si[i], sj[j]), 0.f);
            float uni   = (li[i] + lj[j]) - inter;
            float iou   = inter / uni;
            bool msk = ((iou > 0.2f) && (ri[i] != rj[j])) || (cosv <= 0.2f);
            mb[((size_t)ri[i] << 10) + rj[j]] = msk ? 1 : 0;
        }
    }
}

// ---------------------------------------------------------------------------
// Kernel 4: masked attention, flash-style online softmax + residual
// block = 256 threads handles (b, head, 64 query rows); 16 j-tiles of 64
// smem = Qs(16K) + KV(16K, K then V per tile) + S(16K) = 48KB exactly
// ---------------------------------------------------------------------------
__global__ void __launch_bounds__(256) attn_kernel(
    const float* __restrict__ query, float* __restrict__ out)
{
    int b = blockIdx.z, h = blockIdx.y, i0 = blockIdx.x * 64;

    __shared__ float Qs[64][64];   // [k][i], pre-scaled by 1/8
    __shared__ float KV[64][64];   // K phase: [k][j]; V phase: [j][c]
    __shared__ float S [64][64];   // p [i][j]

    int tid = threadIdx.x;
    int tx = tid & 15, ty = tid >> 4;

    // load Q tile (scaled by 1/sqrt(dh)=0.125), transposed [k][i]
    const float* Qbase = g_Q + ((size_t)(b*LQ + i0) * DD) + h*DH;
    #pragma unroll
    for (int q = 0; q < 4; ++q) {
        int idx = tid + q*256;         // 0..1023
        int r   = idx >> 4;            // 0..63
        int k4  = (idx & 15) << 2;     // 0..60
        float4 v = *(const float4*)(Qbase + (size_t)r*DD + k4);
        Qs[k4+0][r] = v.x*0.125f; Qs[k4+1][r] = v.y*0.125f;
        Qs[k4+2][r] = v.z*0.125f; Qs[k4+3][r] = v.w*0.125f;
    }

    float m_r[4], l_r[4], acc[4][4];
    #pragma unroll
    for (int u = 0; u < 4; ++u) {
        m_r[u] = -1e30f; l_r[u] = 0.f;
        #pragma unroll
        for (int v = 0; v < 4; ++v) acc[u][v] = 0.f;
    }

    for (int jt = 0; jt < LQ/64; ++jt) {
        int j0 = jt * 64;
        __syncthreads();                              // prev-iter S/KV reads done
        // load K tile transposed [k][j]
        const float* Kbase = g_K + ((size_t)(b*LQ + j0) * DD) + h*DH;
        #pragma unroll
        for (int q = 0; q < 4; ++q) {
            int idx = tid + q*256;
            int r   = idx >> 4;
            int k4  = (idx & 15) << 2;
            float4 v = *(const float4*)(Kbase + (size_t)r*DD + k4);
            KV[k4+0][r] = v.x; KV[k4+1][r] = v.y;
            KV[k4+2][r] = v.z; KV[k4+3][r] = v.w;
        }
        __syncthreads();

        // S = Q K^T  (thread: rows ty*4..+3, cols tx*4..+3)
        float s[4][4];
        #pragma unroll
        for (int u = 0; u < 4; ++u)
            #pragma unroll
            for (int v = 0; v < 4; ++v) s[u][v] = 0.f;
        #pragma unroll
        for (int k = 0; k < 64; ++k) {
            float4 qv = *(const float4*)&Qs[k][ty*4];
            float4 kv = *(const float4*)&KV[k][tx*4];
            float qa[4] = {qv.x, qv.y, qv.z, qv.w};
            float ka[4] = {kv.x, kv.y, kv.z, kv.w};
            #pragma unroll
            for (int u = 0; u < 4; ++u)
                #pragma unroll
                for (int v = 0; v < 4; ++v) s[u][v] += qa[u] * ka[v];
        }

        // apply mask
        const unsigned char* mrow = g_mask + ((size_t)b << 20)
                                  + ((size_t)i0 << 10) + j0 + tx*4;
        #pragma unroll
        for (int u = 0; u < 4; ++u) {
            uchar4 mk = *(const uchar4*)(mrow + (size_t)(ty*4+u) * 1024);
            if (mk.x) s[u][0] = -1e30f;
            if (mk.y) s[u][1] = -1e30f;
            if (mk.z) s[u][2] = -1e30f;
            if (mk.w) s[u][3] = -1e30f;
        }

        // online softmax stats (16-lane shuffle groups share a row set)
        float alpha[4];
        #pragma unroll
        for (int u = 0; u < 4; ++u) {
            float pm = fmaxf(fmaxf(s[u][0], s[u][1]), fmaxf(s[u][2], s[u][3]));
            #pragma unroll
            for (int o = 1; o < 16; o <<= 1)
                pm = fmaxf(pm, __shfl_xor_sync(0xffffffffu, pm, o));
            float mn = fmaxf(m_r[u], pm);
            alpha[u] = expf(m_r[u] - mn);
            float ps = 0.f;
            #pragma unroll
            for (int v = 0; v < 4; ++v) {
                float p = expf(s[u][v] - mn);
                if (s[u][v] < -1e29f) p = 0.f;   // guard fully-masked tiles
                s[u][v] = p;
                ps += p;
            }
            #pragma unroll
            for (int o = 1; o < 16; o <<= 1)
                ps += __shfl_xor_sync(0xffffffffu, ps, o);
            l_r[u] = l_r[u] * alpha[u] + ps;
            m_r[u] = mn;
        }
        // rescale accumulators
        #pragma unroll
        for (int u = 0; u < 4; ++u)
            #pragma unroll
            for (int v = 0; v < 4; ++v) acc[u][v] *= alpha[u];

        // store p to smem
        #pragma unroll
        for (int u = 0; u < 4; ++u)
            *(float4*)&S[ty*4+u][tx*4] = make_float4(s[u][0], s[u][1], s[u][2], s[u][3]);
        __syncthreads();                              // KV(K) reads + S writes done

        // load V tile [j][c] over KV
        const float* Vbase = g_V + ((size_t)(b*LQ + j0) * DD) + h*DH;
        #pragma unroll
        for (int q = 0; q < 4; ++q) {
            int idx = tid + q*256;
            int r   = idx >> 4;
            int c4  = (idx & 15) << 2;
            *(float4*)&KV[r][c4] = *(const float4*)(Vbase + (size_t)r*DD + c4);
        }
        __syncthreads();

        // acc += P @ V
        #pragma unroll
        for (int j = 0; j < 64; ++j) {
            float4 vv = *(const float4*)&KV[j][tx*4];
            float va[4] = {vv.x, vv.y, vv.z, vv.w};
            #pragma unroll
            for (int u = 0; u < 4; ++u) {
                float p = S[ty*4+u][j];
                #pragma unroll
                for (int v = 0; v < 4; ++v) acc[u][v] += p * va[v];
            }
        }
    }

    // finalize: /l, + residual h, write [Lq, bz, d]
    #pragma unroll
    for (int u = 0; u < 4; ++u) {
        int i = i0 + ty*4 + u;
        float inv_l = 1.f / l_r[u];
        size_t off = (size_t)i*(BZ*DD) + (size_t)b*DD + h*DH + tx*4;
        float4 rv = *(const float4*)(query + off);
        float4 o;
        o.x = acc[u][0]*inv_l + rv.x;
        o.y = acc[u][1]*inv_l + rv.y;
        o.z = acc[u][2]*inv_l + rv.z;
        o.w = acc[u][3]*inv_l + rv.w;
        *(float4*)(out + off) = o;
    }
}

// ---------------------------------------------------------------------------
extern "C" void kernel_launch(void* const* d_in, const int* in_sizes, int n_in,
                              void* d_out, int out_size)
{
    const float* query    = (const float*)d_in[0];
    const float* segments = (const float*)d_in[1];
    const float* Wq = (const float*)d_in[2];
    const float* bq = (const float*)d_in[3];
    const float* Wk = (const float*)d_in[4];
    const float* bk = (const float*)d_in[5];
    const float* Wv = (const float*)d_in[6];
    const float* bv = (const float*)d_in[7];
    float* out = (float*)d_out;

    norms_kernel<<<MTOT/8, 256>>>(query);
    qkv_kernel  <<<dim3(DD/128, MTOT/128, 3), 256>>>(query, Wq, bq, Wk, bk, Wv, bv);
    mask_kernel <<<dim3(LQ/128, LQ/128, BZ), 256>>>(query, segments);
    attn_kernel <<<dim3(LQ/64, NH, BZ), 256>>>(query, out);
}

// round 3
// speedup vs baseline: 3.4325x; 3.4325x over previous
#include <cuda_runtime.h>
#include <math.h>

#define LQ   1024
#define BZ   8
#define DD   512
#define NH   8
#define DH   64
#define MTOT (BZ*LQ)   // 8192

// Scratch (allocation-free rule: device globals)
__device__ float g_Q[BZ*LQ*DD];
__device__ float g_K[BZ*LQ*DD];
__device__ float g_V[BZ*LQ*DD];
__device__ float g_invn[BZ*LQ];
__device__ int   g_cnt[BZ*LQ];
__device__ int   g_idx[(size_t)BZ*LQ*LQ];   // per-row valid-key lists (exact worst case)

// ---------------------------------------------------------------------------
// Kernel 1: per-row inverse norms of h  +  zero the valid-list counters
// ---------------------------------------------------------------------------
__global__ void __launch_bounds__(256) norms_kernel(const float* __restrict__ query)
{
    int m    = blockIdx.x * 8 + (threadIdx.x >> 5);   // row id = b*1024+i
    int lane = threadIdx.x & 31;
    if (threadIdx.x < 8) g_cnt[blockIdx.x * 8 + threadIdx.x] = 0;
    int b = m >> 10, i = m & 1023;
    const float* p = query + (size_t)i * (BZ*DD) + (size_t)b * DD;
    float ss = 0.f;
    #pragma unroll
    for (int j = 0; j < 16; ++j) {
        float v = p[lane + j*32];
        ss += v * v;
    }
    #pragma unroll
    for (int o = 16; o > 0; o >>= 1) ss += __shfl_xor_sync(0xffffffffu, ss, o);
    if (lane == 0) g_invn[m] = 1.f / fmaxf(sqrtf(ss), 1e-8f);
}

// ---------------------------------------------------------------------------
// Kernel 2: QKV projections.  C[m,n] = sum_k h[m,k]*W[n,k] + bias[n]
// 128x128 tile, BK=16, 256 threads, 8x8 micro, double-buffered smem
// ---------------------------------------------------------------------------
__global__ void __launch_bounds__(256) qkv_kernel(
    const float* __restrict__ query,
    const float* __restrict__ Wq, const float* __restrict__ bq,
    const float* __restrict__ Wk, const float* __restrict__ bk,
    const float* __restrict__ Wv, const float* __restrict__ bv)
{
    const float* W; const float* bias; float* out;
    if      (blockIdx.z == 0) { W = Wq; bias = bq; out = g_Q; }
    else if (blockIdx.z == 1) { W = Wk; bias = bk; out = g_K; }
    else                      { W = Wv; bias = bv; out = g_V; }

    __shared__ float As[2][16][128];   // [buf][k][m]
    __shared__ float Bs[2][16][128];   // [buf][k][n]

    int tid = threadIdx.x;
    int tx = tid & 15, ty = tid >> 4;
    int m0 = blockIdx.y * 128, n0 = blockIdx.x * 128;

    // per-thread load coords (2 quads)
    int rowL[2], kkL[2];
    size_t aoff[2], boff[2];
    #pragma unroll
    for (int q = 0; q < 2; ++q) {
        int f = tid + q*256;
        rowL[q] = f >> 2;
        kkL[q]  = (f & 3) << 2;
        int m = m0 + rowL[q]; int b = m >> 10; int i = m & 1023;
        aoff[q] = (size_t)i*(BZ*DD) + (size_t)b*DD + kkL[q];
        boff[q] = (size_t)(n0 + rowL[q])*DD + kkL[q];
    }

    float acc[8][8];
    #pragma unroll
    for (int i = 0; i < 8; ++i)
        #pragma unroll
        for (int j = 0; j < 8; ++j) acc[i][j] = 0.f;

    // preload tile 0
    #pragma unroll
    for (int q = 0; q < 2; ++q) {
        float4 va = *(const float4*)(query + aoff[q]);
        As[0][kkL[q]+0][rowL[q]] = va.x; As[0][kkL[q]+1][rowL[q]] = va.y;
        As[0][kkL[q]+2][rowL[q]] = va.z; As[0][kkL[q]+3][rowL[q]] = va.w;
        float4 vb = *(const float4*)(W + boff[q]);
        Bs[0][kkL[q]+0][rowL[q]] = vb.x; Bs[0][kkL[q]+1][rowL[q]] = vb.y;
        Bs[0][kkL[q]+2][rowL[q]] = vb.z; Bs[0][kkL[q]+3][rowL[q]] = vb.w;
    }
    __syncthreads();

    for (int kt = 0; kt < DD/16; ++kt) {
        int cur = kt & 1, nxt = kt + 1;
        float4 pa[2], pb[2];
        if (nxt < DD/16) {
            int k0 = nxt * 16;
            #pragma unroll
            for (int q = 0; q < 2; ++q) {
                pa[q] = *(const float4*)(query + aoff[q] + k0);
                pb[q] = *(const float4*)(W + boff[q] + k0);
            }
        }
        #pragma unroll
        for (int k = 0; k < 16; ++k) {
            float a[8], bb[8];
            *(float4*)(a)    = *(const float4*)&As[cur][k][ty*4];
            *(float4*)(a+4)  = *(const float4*)&As[cur][k][64 + ty*4];
            *(float4*)(bb)   = *(const float4*)&Bs[cur][k][tx*4];
            *(float4*)(bb+4) = *(const float4*)&Bs[cur][k][64 + tx*4];
            #pragma unroll
            for (int i = 0; i < 8; ++i)
                #pragma unroll
                for (int j = 0; j < 8; ++j) acc[i][j] += a[i] * bb[j];
        }
        if (nxt < DD/16) {
            int nb = nxt & 1;
            #pragma unroll
            for (int q = 0; q < 2; ++q) {
                As[nb][kkL[q]+0][rowL[q]] = pa[q].x; As[nb][kkL[q]+1][rowL[q]] = pa[q].y;
                As[nb][kkL[q]+2][rowL[q]] = pa[q].z; As[nb][kkL[q]+3][rowL[q]] = pa[q].w;
                Bs[nb][kkL[q]+0][rowL[q]] = pb[q].x; Bs[nb][kkL[q]+1][rowL[q]] = pb[q].y;
                Bs[nb][kkL[q]+2][rowL[q]] = pb[q].z; Bs[nb][kkL[q]+3][rowL[q]] = pb[q].w;
            }
            __syncthreads();
        }
    }

    // epilogue: + bias, store
    #pragma unroll
    for (int i = 0; i < 8; ++i) {
        int r = (i < 4) ? (ty*4 + i) : (64 + ty*4 + (i-4));
        int m = m0 + r;
        #pragma unroll
        for (int jh = 0; jh < 2; ++jh) {
            int c = (jh == 0) ? (tx*4) : (64 + tx*4);
            float4 bv4 = *(const float4*)(bias + n0 + c);
            float4 o;
            o.x = acc[i][jh*4+0] + bv4.x;
            o.y = acc[i][jh*4+1] + bv4.y;
            o.z = acc[i][jh*4+2] + bv4.z;
            o.w = acc[i][jh*4+3] + bv4.w;
            *(float4*)(out + (size_t)m*DD + n0 + c) = o;
        }
    }
}

// ---------------------------------------------------------------------------
// Kernel 3: cos GEMM (h·hT) fused with IoU + thresholds -> per-row valid lists
// valid(i,j) = (iou<=0.2 || i==j) && cos>0.2      (= !mask)
// ---------------------------------------------------------------------------
__global__ void __launch_bounds__(256) mask_kernel(
    const float* __restrict__ query, const float* __restrict__ segments)
{
    int b = blockIdx.z;
    __shared__ float As[2][16][128];
    __shared__ float Bs[2][16][128];

    int tid = threadIdx.x;
    int tx = tid & 15, ty = tid >> 4;
    int i0 = blockIdx.y * 128, j0 = blockIdx.x * 128;

    const float* qb = query + (size_t)b * DD;   // + row*(BZ*DD)

    int rowL[2], kkL[2];
    size_t aoff[2], boff[2];
    #pragma unroll
    for (int q = 0; q < 2; ++q) {
        int f = tid + q*256;
        rowL[q] = f >> 2;
        kkL[q]  = (f & 3) << 2;
        aoff[q] = (size_t)(i0 + rowL[q])*(BZ*DD) + kkL[q];
        boff[q] = (size_t)(j0 + rowL[q])*(BZ*DD) + kkL[q];
    }

    float acc[8][8];
    #pragma unroll
    for (int i = 0; i < 8; ++i)
        #pragma unroll
        for (int j = 0; j < 8; ++j) acc[i][j] = 0.f;

    #pragma unroll
    for (int q = 0; q < 2; ++q) {
        float4 va = *(const float4*)(qb + aoff[q]);
        As[0][kkL[q]+0][rowL[q]] = va.x; As[0][kkL[q]+1][rowL[q]] = va.y;
        As[0][kkL[q]+2][rowL[q]] = va.z; As[0][kkL[q]+3][rowL[q]] = va.w;
        float4 vb = *(const float4*)(qb + boff[q]);
        Bs[0][kkL[q]+0][rowL[q]] = vb.x; Bs[0][kkL[q]+1][rowL[q]] = vb.y;
        Bs[0][kkL[q]+2][rowL[q]] = vb.z; Bs[0][kkL[q]+3][rowL[q]] = vb.w;
    }
    __syncthreads();

    for (int kt = 0; kt < DD/16; ++kt) {
        int cur = kt & 1, nxt = kt + 1;
        float4 pa[2], pb[2];
        if (nxt < DD/16) {
            int k0 = nxt * 16;
            #pragma unroll
            for (int q = 0; q < 2; ++q) {
                pa[q] = *(const float4*)(qb + aoff[q] + k0);
                pb[q] = *(const float4*)(qb + boff[q] + k0);
            }
        }
        #pragma unroll
        for (int k = 0; k < 16; ++k) {
            float a[8], bb[8];
            *(float4*)(a)    = *(const float4*)&As[cur][k][ty*4];
            *(float4*)(a+4)  = *(const float4*)&As[cur][k][64 + ty*4];
            *(float4*)(bb)   = *(const float4*)&Bs[cur][k][tx*4];
            *(float4*)(bb+4) = *(const float4*)&Bs[cur][k][64 + tx*4];
            #pragma unroll
            for (int i = 0; i < 8; ++i)
                #pragma unroll
                for (int j = 0; j < 8; ++j) acc[i][j] += a[i] * bb[j];
        }
        if (nxt < DD/16) {
            int nb = nxt & 1;
            #pragma unroll
            for (int q = 0; q < 2; ++q) {
                As[nb][kkL[q]+0][rowL[q]] = pa[q].x; As[nb][kkL[q]+1][rowL[q]] = pa[q].y;
                As[nb][kkL[q]+2][rowL[q]] = pa[q].z; As[nb][kkL[q]+3][rowL[q]] = pa[q].w;
                Bs[nb][kkL[q]+0][rowL[q]] = pb[q].x; Bs[nb][kkL[q]+1][rowL[q]] = pb[q].y;
                Bs[nb][kkL[q]+2][rowL[q]] = pb[q].z; Bs[nb][kkL[q]+3][rowL[q]] = pb[q].w;
            }
            __syncthreads();
        }
    }

    // epilogue: cos + iou + thresholds -> append valid j to row list
    const float* seg = segments + (size_t)b * LQ * 2;
    float ni[8], si[8], ei[8], li[8];
    float nj[8], sj[8], ej[8], lj[8];
    int   ri[8], rj[8];
    #pragma unroll
    for (int i = 0; i < 8; ++i) {
        int r = (i < 4) ? (ty*4 + i) : (64 + ty*4 + (i-4));
        int gi = i0 + r;
        ri[i] = gi;
        ni[i] = g_invn[b*LQ + gi];
        float cc = seg[gi*2], ll = seg[gi*2+1];
        si[i] = cc - ll*0.5f; ei[i] = cc + ll*0.5f; li[i] = ll;
    }
    #pragma unroll
    for (int j = 0; j < 8; ++j) {
        int c = (j < 4) ? (tx*4 + j) : (64 + tx*4 + (j-4));
        int gj = j0 + c;
        rj[j] = gj;
        nj[j] = g_invn[b*LQ + gj];
        float cc = seg[gj*2], ll = seg[gj*2+1];
        sj[j] = cc - ll*0.5f; ej[j] = cc + ll*0.5f; lj[j] = ll;
    }
    #pragma unroll
    for (int i = 0; i < 8; ++i) {
        #pragma unroll
        for (int j = 0; j < 8; ++j) {
            float cosv  = acc[i][j] * ni[i] * nj[j];
            float inter = fmaxf(fminf(ei[i], ej[j]) - fmaxf(si[i], sj[j]), 0.f);
            float uni   = (li[i] + lj[j]) - inter;
            float iou   = inter / uni;
            bool valid = ((iou <= 0.2f) || (ri[i] == rj[j])) && (cosv > 0.2f);
            if (valid) {
                int rid = b*LQ + ri[i];
                int p = atomicAdd(&g_cnt[rid], 1);
                g_idx[((size_t)rid << 10) + p] = rj[j];
            }
        }
    }
}

// ---------------------------------------------------------------------------
// Kernel 4: sparse masked attention + residual.
// One block per (b,i) row; one warp per head. Exact softmax over the valid
// key list (typically ~1 key; worst case 1024 handled by the loops).
// ---------------------------------------------------------------------------
__global__ void __launch_bounds__(256) sattn_kernel(
    const float* __restrict__ query, float* __restrict__ out)
{
    __shared__ float sc[NH][LQ];    // 32KB score buffer (worst case)

    int row = blockIdx.x;           // b*1024 + i
    int b = row >> 10, i = row & 1023;
    int h = threadIdx.x >> 5, lane = threadIdx.x & 31;

    int c = g_cnt[row];
    const int* idx = g_idx + ((size_t)row << 10);

    const float* Qr = g_Q + (size_t)row * DD + h*DH;
    float2 q = *(const float2*)(Qr + lane*2);

    // scores (serial over keys; c is tiny in practice)
    for (int t = 0; t < c; ++t) {
        int j = idx[t];
        const float* Kr = g_K + (size_t)(b*LQ + j) * DD + h*DH;
        float2 k = *(const float2*)(Kr + lane*2);
        float s = q.x*k.x + q.y*k.y;
        #pragma unroll
        for (int o = 16; o > 0; o >>= 1) s += __shfl_xor_sync(0xffffffffu, s, o);
        if (lane == 0) sc[h][t] = s * 0.125f;   // 1/sqrt(64)
    }
    __syncwarp();

    // softmax over c entries (lane-parallel)
    float m = -1e30f;
    for (int t = lane; t < c; t += 32) m = fmaxf(m, sc[h][t]);
    #pragma unroll
    for (int o = 16; o > 0; o >>= 1) m = fmaxf(m, __shfl_xor_sync(0xffffffffu, m, o));
    float l = 0.f;
    for (int t = lane; t < c; t += 32) {
        float p = expf(sc[h][t] - m);
        sc[h][t] = p;
        l += p;
    }
    #pragma unroll
    for (int o = 16; o > 0; o >>= 1) l += __shfl_xor_sync(0xffffffffu, l, o);
    __syncwarp();

    // gather V
    float o0 = 0.f, o1 = 0.f;
    for (int t = 0; t < c; ++t) {
        int j = idx[t];
        float p = sc[h][t];
        const float* Vr = g_V + (size_t)(b*LQ + j) * DD + h*DH;
        float2 v = *(const float2*)(Vr + lane*2);
        o0 += p * v.x;
        o1 += p * v.y;
    }
    float invl = 1.f / l;

    size_t off = (size_t)i*(BZ*DD) + (size_t)b*DD + h*DH + lane*2;
    float2 r = *(const float2*)(query + off);
    float2 ov;
    ov.x = o0*invl + r.x;
    ov.y = o1*invl + r.y;
    *(float2*)(out + off) = ov;
}

// ---------------------------------------------------------------------------
extern "C" void kernel_launch(void* const* d_in, const int* in_sizes, int n_in,
                              void* d_out, int out_size)
{
    const float* query    = (const float*)d_in[0];
    const float* segments = (const float*)d_in[1];
    const float* Wq = (const float*)d_in[2];
    const float* bq = (const float*)d_in[3];
    const float* Wk = (const float*)d_in[4];
    const float* bk = (const float*)d_in[5];
    const float* Wv = (const float*)d_in[6];
    const float* bv = (const float*)d_in[7];
    float* out = (float*)d_out;

    norms_kernel<<<MTOT/8, 256>>>(query);
    qkv_kernel  <<<dim3(DD/128, MTOT/128, 3), 256>>>(query, Wq, bq, Wk, bk, Wv, bv);
    mask_kernel <<<dim3(LQ/128, LQ/128, BZ), 256>>>(query, segments);
    sattn_kernel<<<MTOT, 256>>>(query, out);
}

// round 6
// speedup vs baseline: 6.3430x; 1.8479x over previous
#include <cuda_runtime.h>
#include <cuda_bf16.h>
#include <math.h>
#include <stdint.h>

#define LQ   1024
#define BZ   8
#define DD   512
#define NH   8
#define DH   64
#define MTOT (BZ*LQ)   // 8192

// GEMM tiling
#define LDSP        40                      // padded row length in bf16 (32 data + 8)
#define PLANE_BYTES (128*LDSP*2)            // 10240
#define STAGE_BYTES (4*PLANE_BYTES)         // 40960  (Ahi,Alo,Bhi,Blo)
#define GSMEM_TOTAL (2*STAGE_BYTES)         // 81920
#define NSTAGES     16                      // K=512 / BK=32

// ---------------- device scratch (allocation-free rule) ----------------
__device__ float g_Q[BZ*LQ*DD];
__device__ float g_K[BZ*LQ*DD];
__device__ float g_V[BZ*LQ*DD];
__device__ float g_invn[BZ*LQ];
__device__ int   g_cnt[BZ*LQ];
__device__ int   g_idx[(size_t)BZ*LQ*LQ];
__device__ __nv_bfloat16 g_hhi[MTOT*DD], g_hlo[MTOT*DD];
__device__ __nv_bfloat16 g_Whi[3*DD*DD], g_Wlo[3*DD*DD];

// ---------------- helpers ----------------
__device__ __forceinline__ uint32_t smem_u32(const void* p) {
    uint32_t a;
    asm("{ .reg .u64 t; cvta.to.shared.u64 t, %1; cvt.u32.u64 %0, t; }" : "=r"(a) : "l"(p));
    return a;
}
__device__ __forceinline__ void cp_async16(uint32_t dst, const void* src) {
    asm volatile("cp.async.cg.shared.global [%0], [%1], 16;" :: "r"(dst), "l"(src) : "memory");
}
__device__ __forceinline__ void ldsm_x4(uint32_t* r, uint32_t addr) {
    asm volatile("ldmatrix.sync.aligned.m8n8.x4.shared.b16 {%0,%1,%2,%3}, [%4];"
                 : "=r"(r[0]), "=r"(r[1]), "=r"(r[2]), "=r"(r[3]) : "r"(addr));
}
__device__ __forceinline__ void ldsm_x2(uint32_t& r0, uint32_t& r1, uint32_t addr) {
    asm volatile("ldmatrix.sync.aligned.m8n8.x2.shared.b16 {%0,%1}, [%2];"
                 : "=r"(r0), "=r"(r1) : "r"(addr));
}
__device__ __forceinline__ void mma_bf16(float* c, const uint32_t* a, uint32_t b0, uint32_t b1) {
    asm volatile(
        "mma.sync.aligned.m16n8k16.row.col.f32.bf16.bf16.f32 "
        "{%0,%1,%2,%3}, {%4,%5,%6,%7}, {%8,%9}, {%0,%1,%2,%3};"
        : "+f"(c[0]), "+f"(c[1]), "+f"(c[2]), "+f"(c[3])
        : "r"(a[0]), "r"(a[1]), "r"(a[2]), "r"(a[3]), "r"(b0), "r"(b1));
}

// ---------------------------------------------------------------------------
// Kernel 1: norms + counter init
// ---------------------------------------------------------------------------
__global__ void __launch_bounds__(256) norms_kernel(const float* __restrict__ query)
{
    int m    = blockIdx.x * 8 + (threadIdx.x >> 5);
    int lane = threadIdx.x & 31;
    if (threadIdx.x < 8) g_cnt[blockIdx.x * 8 + threadIdx.x] = 0;
    int b = m >> 10, i = m & 1023;
    const float* p = query + (size_t)i * (BZ*DD) + (size_t)b * DD;
    float ss = 0.f;
    #pragma unroll
    for (int j = 0; j < 16; ++j) { float v = p[lane + j*32]; ss += v*v; }
    #pragma unroll
    for (int o = 16; o > 0; o >>= 1) ss += __shfl_xor_sync(0xffffffffu, ss, o);
    if (lane == 0) g_invn[m] = 1.f / fmaxf(sqrtf(ss), 1e-8f);
}

// ---------------------------------------------------------------------------
// Kernel 2: split h and W into bf16 hi/lo planes
// ---------------------------------------------------------------------------
__device__ __forceinline__ void split2(float x, __nv_bfloat16& h, __nv_bfloat16& l) {
    h = __float2bfloat16(x);
    l = __float2bfloat16(x - __bfloat162float(h));
}

__global__ void __launch_bounds__(256) convert_kernel(
    const float* __restrict__ query,
    const float* __restrict__ Wq, const float* __restrict__ Wk, const float* __restrict__ Wv)
{
    int idx = blockIdx.x * 256 + threadIdx.x;     // one float4
    float4 v; size_t dst;
    if (idx < 1048576) {                          // h: 8192 rows x 128 float4
        int m = idx >> 7, k4 = (idx & 127) << 2;
        int b = m >> 10, i = m & 1023;
        v = *(const float4*)(query + (size_t)i*(BZ*DD) + (size_t)b*DD + k4);
        dst = (size_t)m * DD + k4;
        __nv_bfloat16 h0,l0,h1,l1,h2,l2,h3,l3;
        split2(v.x,h0,l0); split2(v.y,h1,l1); split2(v.z,h2,l2); split2(v.w,h3,l3);
        g_hhi[dst+0]=h0; g_hhi[dst+1]=h1; g_hhi[dst+2]=h2; g_hhi[dst+3]=h3;
        g_hlo[dst+0]=l0; g_hlo[dst+1]=l1; g_hlo[dst+2]=l2; g_hlo[dst+3]=l3;
    } else if (idx < 1048576 + 196608) {          // W: 3 x 65536 float4
        int e = idx - 1048576;
        int z = e >> 16, r = e & 65535;
        const float* W = (z == 0) ? Wq : ((z == 1) ? Wk : Wv);
        v = *(const float4*)(W + (size_t)r * 4);
        dst = (size_t)z * (DD*DD) + (size_t)r * 4;
        __nv_bfloat16 h0,l0,h1,l1,h2,l2,h3,l3;
        split2(v.x,h0,l0); split2(v.y,h1,l1); split2(v.z,h2,l2); split2(v.w,h3,l3);
        g_Whi[dst+0]=h0; g_Whi[dst+1]=h1; g_Whi[dst+2]=h2; g_Whi[dst+3]=h3;
        g_Wlo[dst+0]=l0; g_Wlo[dst+1]=l1; g_Wlo[dst+2]=l2; g_Wlo[dst+3]=l3;
    }
}

// ---------------------------------------------------------------------------
// Shared HMMA mainloop: acc[2][8][4] += A[128xK] * B[128xK]^T (3 split terms)
// Block 256 thr = 8 warps (4M x 2N); warp tile 32x64; BK=32; K=512.
// ---------------------------------------------------------------------------
__device__ __forceinline__ void hmma_mainloop(char* smem,
    const __nv_bfloat16* __restrict__ Ahi, const __nv_bfloat16* __restrict__ Alo,
    const __nv_bfloat16* __restrict__ Bhi, const __nv_bfloat16* __restrict__ Blo,
    float acc[2][8][4])
{
    const __nv_bfloat16* gsrc[4] = { Ahi, Alo, Bhi, Blo };
    int tid = threadIdx.x, lane = tid & 31, wid = tid >> 5;
    int warp_m = wid & 3, warp_n = wid >> 2;
    uint32_t sbase = smem_u32(smem);

    // precompute per-thread cp.async coords (8 chunks of 16B / stage)
    int ca[8], crow[8], cch[8];
    #pragma unroll
    for (int it = 0; it < 8; ++it) {
        int c = tid + it * 256;            // 0..2047
        ca[it]   = c >> 9;                 // array 0..3
        crow[it] = (c >> 2) & 127;
        cch[it]  = c & 3;
    }

    // ldmatrix base offsets (bytes, within a plane)
    int r8 = lane & 7, g = lane >> 3;
    uint32_t aoff[2];
    #pragma unroll
    for (int mf = 0; mf < 2; ++mf)
        aoff[mf] = ((warp_m*32 + mf*16 + r8 + (g & 1)*8) * LDSP + ((g >> 1) & 1)*8) * 2;
    int qb = lane & 15, rb = qb & 7, gb = qb >> 3;
    uint32_t boff[8];
    #pragma unroll
    for (int jf = 0; jf < 8; ++jf)
        boff[jf] = ((warp_n*64 + jf*8 + rb) * LDSP + gb*8) * 2;

    // preload stage 0
    #pragma unroll
    for (int it = 0; it < 8; ++it) {
        uint32_t dst = sbase + ca[it]*PLANE_BYTES + crow[it]*(LDSP*2) + cch[it]*16;
        cp_async16(dst, gsrc[ca[it]] + (size_t)crow[it]*DD + cch[it]*8);
    }
    asm volatile("cp.async.commit_group;" ::: "memory");

    for (int s = 0; s < NSTAGES; ++s) {
        if (s + 1 < NSTAGES) {
            int k0 = (s + 1) * 32;
            uint32_t dbase = sbase + ((s + 1) & 1) * STAGE_BYTES;
            #pragma unroll
            for (int it = 0; it < 8; ++it) {
                uint32_t dst = dbase + ca[it]*PLANE_BYTES + crow[it]*(LDSP*2) + cch[it]*16;
                cp_async16(dst, gsrc[ca[it]] + (size_t)crow[it]*DD + k0 + cch[it]*8);
            }
            asm volatile("cp.async.commit_group;" ::: "memory");
            asm volatile("cp.async.wait_group 1;" ::: "memory");
        } else {
            asm volatile("cp.async.wait_group 0;" ::: "memory");
        }
        __syncthreads();

        uint32_t st = sbase + (s & 1) * STAGE_BYTES;
        #pragma unroll
        for (int ks = 0; ks < 2; ++ks) {
            uint32_t kofs = ks * 32;              // 16 bf16 = 32 bytes
            uint32_t ah[2][4], al[2][4];
            #pragma unroll
            for (int mf = 0; mf < 2; ++mf) {
                ldsm_x4(ah[mf], st + 0*PLANE_BYTES + aoff[mf] + kofs);
                ldsm_x4(al[mf], st + 1*PLANE_BYTES + aoff[mf] + kofs);
            }
            #pragma unroll
            for (int jf = 0; jf < 8; ++jf) {
                uint32_t bh0, bh1, bl0, bl1;
                ldsm_x2(bh0, bh1, st + 2*PLANE_BYTES + boff[jf] + kofs);
                ldsm_x2(bl0, bl1, st + 3*PLANE_BYTES + boff[jf] + kofs);
                #pragma unroll
                for (int mf = 0; mf < 2; ++mf) {
                    mma_bf16(acc[mf][jf], ah[mf], bh0, bh1);   // hi*hi
                    mma_bf16(acc[mf][jf], ah[mf], bl0, bl1);   // hi*lo
                    mma_bf16(acc[mf][jf], al[mf], bh0, bh1);   // lo*hi
                }
            }
        }
        __syncthreads();
    }
}

// ---------------------------------------------------------------------------
// Kernel 3: QKV projection (HMMA)
// ---------------------------------------------------------------------------
__global__ void __launch_bounds__(256) qkv_tc_kernel(
    const float* __restrict__ bq, const float* __restrict__ bk, const float* __restrict__ bv)
{
    extern __shared__ char dynsmem[];
    int z = blockIdx.z;
    int m0 = blockIdx.y * 128, n0 = blockIdx.x * 128;
    const float* bias = (z == 0) ? bq : ((z == 1) ? bk : bv);
    float* out = (z == 0) ? g_Q : ((z == 1) ? g_K : g_V);

    float acc[2][8][4];
    #pragma unroll
    for (int a = 0; a < 2; ++a)
        #pragma unroll
        for (int b = 0; b < 8; ++b)
            #pragma unroll
            for (int c = 0; c < 4; ++c) acc[a][b][c] = 0.f;

    hmma_mainloop(dynsmem,
        g_hhi + (size_t)m0 * DD, g_hlo + (size_t)m0 * DD,
        g_Whi + (size_t)z*(DD*DD) + (size_t)n0 * DD,
        g_Wlo + (size_t)z*(DD*DD) + (size_t)n0 * DD, acc);

    int lane = threadIdx.x & 31, wid = threadIdx.x >> 5;
    int warp_m = wid & 3, warp_n = wid >> 2;
    int row0 = m0 + warp_m*32 + (lane >> 2);
    int col0 = n0 + warp_n*64 + (lane & 3)*2;
    #pragma unroll
    for (int mf = 0; mf < 2; ++mf) {
        #pragma unroll
        for (int jf = 0; jf < 8; ++jf) {
            int cc = col0 + jf*8;
            float2 b2 = *(const float2*)(bias + cc);
            float2 o0, o1;
            o0.x = acc[mf][jf][0] + b2.x; o0.y = acc[mf][jf][1] + b2.y;
            o1.x = acc[mf][jf][2] + b2.x; o1.y = acc[mf][jf][3] + b2.y;
            *(float2*)(out + (size_t)(row0 + mf*16    )*DD + cc) = o0;
            *(float2*)(out + (size_t)(row0 + mf*16 + 8)*DD + cc) = o1;
        }
    }
}

// ---------------------------------------------------------------------------
// Kernel 4: cos GEMM (HMMA) + IoU/threshold epilogue -> valid lists
// ---------------------------------------------------------------------------
__global__ void __launch_bounds__(256) mask_tc_kernel(
    const float* __restrict__ query, const float* __restrict__ segments)
{
    extern __shared__ char dynsmem[];
    int b = blockIdx.z;
    int i0 = blockIdx.y * 128, j0 = blockIdx.x * 128;

    float acc[2][8][4];
    #pragma unroll
    for (int a = 0; a < 2; ++a)
        #pragma unroll
        for (int bb = 0; bb < 8; ++bb)
            #pragma unroll
            for (int c = 0; c < 4; ++c) acc[a][bb][c] = 0.f;

    hmma_mainloop(dynsmem,
        g_hhi + (size_t)(b*LQ + i0) * DD, g_hlo + (size_t)(b*LQ + i0) * DD,
        g_hhi + (size_t)(b*LQ + j0) * DD, g_hlo + (size_t)(b*LQ + j0) * DD, acc);

    int lane = threadIdx.x & 31, wid = threadIdx.x >> 5;
    int warp_m = wid & 3, warp_n = wid >> 2;
    const float* seg = segments + (size_t)b * LQ * 2;

    // 4 owned rows: t = mf*2 + half -> row offset {0,8,16,24}
    int   gi[4], rid[4];
    float ni[4], si[4], ei[4], li[4];
    #pragma unroll
    for (int t = 0; t < 4; ++t) {
        int r = i0 + warp_m*32 + (lane >> 2) + (t >> 1)*16 + (t & 1)*8;
        gi[t] = r; rid[t] = b*LQ + r;
        ni[t] = g_invn[rid[t]];
        float cc = seg[r*2], ll = seg[r*2+1];
        si[t] = cc - ll*0.5f; ei[t] = cc + ll*0.5f; li[t] = ll;
    }

    #pragma unroll
    for (int jf = 0; jf < 8; ++jf) {
        #pragma unroll
        for (int c2 = 0; c2 < 2; ++c2) {
            int gj = j0 + warp_n*64 + jf*8 + (lane & 3)*2 + c2;
            float nj = g_invn[b*LQ + gj];
            float cj = seg[gj*2], lj = seg[gj*2+1];
            float sj = cj - lj*0.5f, ej = cj + lj*0.5f;
            #pragma unroll
            for (int t = 0; t < 4; ++t) {
                float cosv = acc[t >> 1][jf][(t & 1)*2 + c2] * ni[t] * nj;
                if (fabsf(cosv - 0.2f) < 1e-3f) {
                    // exact fp32 recheck (rare)
                    const float* hp = query + (size_t)gi[t]*(BZ*DD) + (size_t)b*DD;
                    const float* hq = query + (size_t)gj   *(BZ*DD) + (size_t)b*DD;
                    float d = 0.f;
                    for (int k = 0; k < DD; ++k) d += hp[k] * hq[k];
                    cosv = d * ni[t] * nj;
                }
                float inter = fmaxf(fminf(ei[t], ej) - fmaxf(si[t], sj), 0.f);
                float uni   = (li[t] + lj) - inter;
                float iou   = inter / uni;
                bool valid = ((iou <= 0.2f) || (gi[t] == gj)) && (cosv > 0.2f);
                if (valid) {
                    int p = atomicAdd(&g_cnt[rid[t]], 1);
                    g_idx[((size_t)rid[t] << 10) + p] = gj;
                }
            }
        }
    }
}

// ---------------------------------------------------------------------------
// Kernel 5: sparse masked attention + residual
// ---------------------------------------------------------------------------
__global__ void __launch_bounds__(256) sattn_kernel(
    const float* __restrict__ query, float* __restrict__ out)
{
    __shared__ float sc[NH][LQ];

    int row = blockIdx.x;
    int b = row >> 10, i = row & 1023;
    int h = threadIdx.x >> 5, lane = threadIdx.x & 31;

    int c = g_cnt[row];
    const int* idx = g_idx + ((size_t)row << 10);

    const float* Qr = g_Q + (size_t)row * DD + h*DH;
    float2 q = *(const float2*)(Qr + lane*2);

    for (int t = 0; t < c; ++t) {
        int j = idx[t];
        const float* Kr = g_K + (size_t)(b*LQ + j) * DD + h*DH;
        float2 k = *(const float2*)(Kr + lane*2);
        float s = q.x*k.x + q.y*k.y;
        #pragma unroll
        for (int o = 16; o > 0; o >>= 1) s += __shfl_xor_sync(0xffffffffu, s, o);
        if (lane == 0) sc[h][t] = s * 0.125f;
    }
    __syncwarp();

    float m = -1e30f;
    for (int t = lane; t < c; t += 32) m = fmaxf(m, sc[h][t]);
    #pragma unroll
    for (int o = 16; o > 0; o >>= 1) m = fmaxf(m, __shfl_xor_sync(0xffffffffu, m, o));
    float l = 0.f;
    for (int t = lane; t < c; t += 32) {
        float p = expf(sc[h][t] - m);
        sc[h][t] = p;
        l += p;
    }
    #pragma unroll
    for (int o = 16; o > 0; o >>= 1) l += __shfl_xor_sync(0xffffffffu, l, o);
    __syncwarp();

    float o0 = 0.f, o1 = 0.f;
    for (int t = 0; t < c; ++t) {
        int j = idx[t];
        float p = sc[h][t];
        const float* Vr = g_V + (size_t)(b*LQ + j) * DD + h*DH;
        float2 v = *(const float2*)(Vr + lane*2);
        o0 += p * v.x;
        o1 += p * v.y;
    }
    float invl = 1.f / l;

    size_t off = (size_t)i*(BZ*DD) + (size_t)b*DD + h*DH + lane*2;
    float2 rv = *(const float2*)(query + off);
    float2 ov;
    ov.x = o0*invl + rv.x;
    ov.y = o1*invl + rv.y;
    *(float2*)(out + off) = ov;
}

// ---------------------------------------------------------------------------
extern "C" void kernel_launch(void* const* d_in, const int* in_sizes, int n_in,
                              void* d_out, int out_size)
{
    const float* query    = (const float*)d_in[0];
    const float* segments = (const float*)d_in[1];
    const float* Wq = (const float*)d_in[2];
    const float* bq = (const float*)d_in[3];
    const float* Wk = (const float*)d_in[4];
    const float* bk = (const float*)d_in[5];
    const float* Wv = (const float*)d_in[6];
    const float* bv = (const float*)d_in[7];
    float* out = (float*)d_out;

    static int attr_done = 0;
    if (!attr_done) {
        cudaFuncSetAttribute(qkv_tc_kernel,  cudaFuncAttributeMaxDynamicSharedMemorySize, GSMEM_TOTAL);
        cudaFuncSetAttribute(mask_tc_kernel, cudaFuncAttributeMaxDynamicSharedMemorySize, GSMEM_TOTAL);
        attr_done = 1;
    }

    norms_kernel  <<<MTOT/8, 256>>>(query);
    convert_kernel<<<(1048576 + 196608 + 255)/256, 256>>>(query, Wq, Wk, Wv);
    qkv_tc_kernel <<<dim3(DD/128, MTOT/128, 3), 256, GSMEM_TOTAL>>>(bq, bk, bv);
    mask_tc_kernel<<<dim3(LQ/128, LQ/128, BZ), 256, GSMEM_TOTAL>>>(query, segments);
    sattn_kernel  <<<MTOT, 256>>>(query, out);
}

// round 7
// speedup vs baseline: 6.8971x; 1.0874x over previous
#include <cuda_runtime.h>
#include <cuda_bf16.h>
#include <math.h>
#include <stdint.h>

#define LQ   1024
#define BZ   8
#define DD   512
#define NH   8
#define DH   64
#define MTOT (BZ*LQ)   // 8192

// GEMM tiling
#define LDSP        40                      // padded row length in bf16 (32 data + 8)
#define PLANE_BYTES (128*LDSP*2)            // 10240
#define NSTAGES     16                      // K=512 / BK=32
#define SMEM_QKV    (2*4*PLANE_BYTES)       // 81920 (dbl-buf, 4 planes)
#define SMEM_MASK   (2*2*PLANE_BYTES)       // 40960 (dbl-buf, 2 planes)

// ---------------- device scratch (allocation-free rule) ----------------
__device__ float g_Q[BZ*LQ*DD];
__device__ float g_K[BZ*LQ*DD];
__device__ float g_V[BZ*LQ*DD];
__device__ float g_invn[BZ*LQ];
__device__ int   g_cnt[BZ*LQ];
__device__ int   g_idx[(size_t)BZ*LQ*LQ];
__device__ __nv_bfloat16 g_hhi[MTOT*DD], g_hlo[MTOT*DD];
__device__ __nv_bfloat16 g_Whi[3*DD*DD], g_Wlo[3*DD*DD];

// ---------------- helpers ----------------
__device__ __forceinline__ uint32_t smem_u32(const void* p) {
    uint32_t a;
    asm("{ .reg .u64 t; cvta.to.shared.u64 t, %1; cvt.u32.u64 %0, t; }" : "=r"(a) : "l"(p));
    return a;
}
__device__ __forceinline__ void cp_async16(uint32_t dst, const void* src) {
    asm volatile("cp.async.cg.shared.global [%0], [%1], 16;" :: "r"(dst), "l"(src) : "memory");
}
__device__ __forceinline__ void ldsm_x4(uint32_t* r, uint32_t addr) {
    asm volatile("ldmatrix.sync.aligned.m8n8.x4.shared.b16 {%0,%1,%2,%3}, [%4];"
                 : "=r"(r[0]), "=r"(r[1]), "=r"(r[2]), "=r"(r[3]) : "r"(addr));
}
__device__ __forceinline__ void ldsm_x2(uint32_t& r0, uint32_t& r1, uint32_t addr) {
    asm volatile("ldmatrix.sync.aligned.m8n8.x2.shared.b16 {%0,%1}, [%2];"
                 : "=r"(r0), "=r"(r1) : "r"(addr));
}
__device__ __forceinline__ void mma_bf16(float* c, const uint32_t* a, uint32_t b0, uint32_t b1) {
    asm volatile(
        "mma.sync.aligned.m16n8k16.row.col.f32.bf16.bf16.f32 "
        "{%0,%1,%2,%3}, {%4,%5,%6,%7}, {%8,%9}, {%0,%1,%2,%3};"
        : "+f"(c[0]), "+f"(c[1]), "+f"(c[2]), "+f"(c[3])
        : "r"(a[0]), "r"(a[1]), "r"(a[2]), "r"(a[3]), "r"(b0), "r"(b1));
}

// ---------------------------------------------------------------------------
// Kernel 1: norms + counter init
// ---------------------------------------------------------------------------
__global__ void __launch_bounds__(256) norms_kernel(const float* __restrict__ query)
{
    int m    = blockIdx.x * 8 + (threadIdx.x >> 5);
    int lane = threadIdx.x & 31;
    if (threadIdx.x < 8) g_cnt[blockIdx.x * 8 + threadIdx.x] = 0;
    int b = m >> 10, i = m & 1023;
    const float* p = query + (size_t)i * (BZ*DD) + (size_t)b * DD;
    float ss = 0.f;
    #pragma unroll
    for (int j = 0; j < 16; ++j) { float v = p[lane + j*32]; ss += v*v; }
    #pragma unroll
    for (int o = 16; o > 0; o >>= 1) ss += __shfl_xor_sync(0xffffffffu, ss, o);
    if (lane == 0) g_invn[m] = 1.f / fmaxf(sqrtf(ss), 1e-8f);
}

// ---------------------------------------------------------------------------
// Kernel 2: split h and W into bf16 hi/lo planes
// ---------------------------------------------------------------------------
__device__ __forceinline__ void split2(float x, __nv_bfloat16& h, __nv_bfloat16& l) {
    h = __float2bfloat16(x);
    l = __float2bfloat16(x - __bfloat162float(h));
}

__global__ void __launch_bounds__(256) convert_kernel(
    const float* __restrict__ query,
    const float* __restrict__ Wq, const float* __restrict__ Wk, const float* __restrict__ Wv)
{
    int idx = blockIdx.x * 256 + threadIdx.x;     // one float4
    float4 v; size_t dst;
    if (idx < 1048576) {                          // h: 8192 rows x 128 float4
        int m = idx >> 7, k4 = (idx & 127) << 2;
        int b = m >> 10, i = m & 1023;
        v = *(const float4*)(query + (size_t)i*(BZ*DD) + (size_t)b*DD + k4);
        dst = (size_t)m * DD + k4;
        __nv_bfloat16 h0,l0,h1,l1,h2,l2,h3,l3;
        split2(v.x,h0,l0); split2(v.y,h1,l1); split2(v.z,h2,l2); split2(v.w,h3,l3);
        g_hhi[dst+0]=h0; g_hhi[dst+1]=h1; g_hhi[dst+2]=h2; g_hhi[dst+3]=h3;
        g_hlo[dst+0]=l0; g_hlo[dst+1]=l1; g_hlo[dst+2]=l2; g_hlo[dst+3]=l3;
    } else if (idx < 1048576 + 196608) {          // W: 3 x 65536 float4
        int e = idx - 1048576;
        int z = e >> 16, r = e & 65535;
        const float* W = (z == 0) ? Wq : ((z == 1) ? Wk : Wv);
        v = *(const float4*)(W + (size_t)r * 4);
        dst = (size_t)z * (DD*DD) + (size_t)r * 4;
        __nv_bfloat16 h0,l0,h1,l1,h2,l2,h3,l3;
        split2(v.x,h0,l0); split2(v.y,h1,l1); split2(v.z,h2,l2); split2(v.w,h3,l3);
        g_Whi[dst+0]=h0; g_Whi[dst+1]=h1; g_Whi[dst+2]=h2; g_Whi[dst+3]=h3;
        g_Wlo[dst+0]=l0; g_Wlo[dst+1]=l1; g_Wlo[dst+2]=l2; g_Wlo[dst+3]=l3;
    }
}

// ---------------------------------------------------------------------------
// HMMA mainloop. SPLIT=true: 3-term bf16 split (planes Ahi,Alo,Bhi,Blo).
// SPLIT=false: single term (planes Ahi,Bhi). Block 256 thr = 8 warps (4Mx2N),
// warp tile 32x64, BK=32, K=512, double-buffered cp.async.
// MMAs issued in independent sweeps of 8 (4 jf x 2 mf) to hide HMMA latency.
// ---------------------------------------------------------------------------
template<bool SPLIT>
__device__ __forceinline__ void hmma_mainloop(char* smem,
    const __nv_bfloat16* __restrict__ Ahi, const __nv_bfloat16* __restrict__ Alo,
    const __nv_bfloat16* __restrict__ Bhi, const __nv_bfloat16* __restrict__ Blo,
    float acc[2][8][4])
{
    constexpr int NP   = SPLIT ? 4 : 2;               // planes per stage
    constexpr int NIT  = NP * 2;                      // cp.async iters (x256 thr)
    constexpr uint32_t STG = NP * PLANE_BYTES;
    constexpr uint32_t BPL = (SPLIT ? 2 : 1) * PLANE_BYTES;   // B-hi plane offset

    const __nv_bfloat16* gsrc[NP];
    gsrc[0] = Ahi;
    if (SPLIT) { gsrc[1] = Alo; gsrc[2] = Bhi; gsrc[3] = Blo; }
    else       { gsrc[1] = Bhi; }

    int tid = threadIdx.x, lane = tid & 31, wid = tid >> 5;
    int warp_m = wid & 3, warp_n = wid >> 2;
    uint32_t sbase = smem_u32(smem);

    // per-thread cp.async coords
    int ca[NIT], crow[NIT], cch[NIT];
    #pragma unroll
    for (int it = 0; it < NIT; ++it) {
        int c = tid + it * 256;
        ca[it]   = c >> 9;
        crow[it] = (c >> 2) & 127;
        cch[it]  = c & 3;
    }

    // ldmatrix base offsets (bytes, within a plane)
    int r8 = lane & 7, g = lane >> 3;
    uint32_t aoff[2];
    #pragma unroll
    for (int mf = 0; mf < 2; ++mf)
        aoff[mf] = ((warp_m*32 + mf*16 + r8 + (g & 1)*8) * LDSP + ((g >> 1) & 1)*8) * 2;
    int qb = lane & 15, rb = qb & 7, gb = qb >> 3;
    uint32_t boff[8];
    #pragma unroll
    for (int jf = 0; jf < 8; ++jf)
        boff[jf] = ((warp_n*64 + jf*8 + rb) * LDSP + gb*8) * 2;

    // preload stage 0
    #pragma unroll
    for (int it = 0; it < NIT; ++it) {
        uint32_t dst = sbase + ca[it]*PLANE_BYTES + crow[it]*(LDSP*2) + cch[it]*16;
        cp_async16(dst, gsrc[ca[it]] + (size_t)crow[it]*DD + cch[it]*8);
    }
    asm volatile("cp.async.commit_group;" ::: "memory");

    for (int s = 0; s < NSTAGES; ++s) {
        if (s + 1 < NSTAGES) {
            int k0 = (s + 1) * 32;
            uint32_t dbase = sbase + ((s + 1) & 1) * STG;
            #pragma unroll
            for (int it = 0; it < NIT; ++it) {
                uint32_t dst = dbase + ca[it]*PLANE_BYTES + crow[it]*(LDSP*2) + cch[it]*16;
                cp_async16(dst, gsrc[ca[it]] + (size_t)crow[it]*DD + k0 + cch[it]*8);
            }
            asm volatile("cp.async.commit_group;" ::: "memory");
            asm volatile("cp.async.wait_group 1;" ::: "memory");
        } else {
            asm volatile("cp.async.wait_group 0;" ::: "memory");
        }
        __syncthreads();

        uint32_t st = sbase + (s & 1) * STG;
        #pragma unroll
        for (int ks = 0; ks < 2; ++ks) {
            uint32_t kofs = ks * 32;
            uint32_t ah[2][4], al[2][4];
            #pragma unroll
            for (int mf = 0; mf < 2; ++mf) {
                ldsm_x4(ah[mf], st + aoff[mf] + kofs);
                if (SPLIT) ldsm_x4(al[mf], st + PLANE_BYTES + aoff[mf] + kofs);
            }
            #pragma unroll
            for (int half = 0; half < 2; ++half) {
                uint32_t bh[4][2], bl[4][2];
                #pragma unroll
                for (int j = 0; j < 4; ++j) {
                    ldsm_x2(bh[j][0], bh[j][1], st + BPL + boff[half*4+j] + kofs);
                    if (SPLIT)
                        ldsm_x2(bl[j][0], bl[j][1], st + 3*PLANE_BYTES + boff[half*4+j] + kofs);
                }
                // term hi*hi — 8 independent MMAs
                #pragma unroll
                for (int j = 0; j < 4; ++j)
                    #pragma unroll
                    for (int mf = 0; mf < 2; ++mf)
                        mma_bf16(acc[mf][half*4+j], ah[mf], bh[j][0], bh[j][1]);
                if (SPLIT) {
                    // term hi*lo
                    #pragma unroll
                    for (int j = 0; j < 4; ++j)
                        #pragma unroll
                        for (int mf = 0; mf < 2; ++mf)
                            mma_bf16(acc[mf][half*4+j], ah[mf], bl[j][0], bl[j][1]);
                    // term lo*hi
                    #pragma unroll
                    for (int j = 0; j < 4; ++j)
                        #pragma unroll
                        for (int mf = 0; mf < 2; ++mf)
                            mma_bf16(acc[mf][half*4+j], al[mf], bh[j][0], bh[j][1]);
                }
            }
        }
        __syncthreads();
    }
}

// ---------------------------------------------------------------------------
// Kernel 3: QKV projection (HMMA, 3-term split)
// ---------------------------------------------------------------------------
__global__ void __launch_bounds__(256) qkv_tc_kernel(
    const float* __restrict__ bq, const float* __restrict__ bk, const float* __restrict__ bv)
{
    extern __shared__ char dynsmem[];
    int z = blockIdx.z;
    int m0 = blockIdx.y * 128, n0 = blockIdx.x * 128;
    const float* bias = (z == 0) ? bq : ((z == 1) ? bk : bv);
    float* out = (z == 0) ? g_Q : ((z == 1) ? g_K : g_V);

    float acc[2][8][4];
    #pragma unroll
    for (int a = 0; a < 2; ++a)
        #pragma unroll
        for (int b = 0; b < 8; ++b)
            #pragma unroll
            for (int c = 0; c < 4; ++c) acc[a][b][c] = 0.f;

    hmma_mainloop<true>(dynsmem,
        g_hhi + (size_t)m0 * DD, g_hlo + (size_t)m0 * DD,
        g_Whi + (size_t)z*(DD*DD) + (size_t)n0 * DD,
        g_Wlo + (size_t)z*(DD*DD) + (size_t)n0 * DD, acc);

    int lane = threadIdx.x & 31, wid = threadIdx.x >> 5;
    int warp_m = wid & 3, warp_n = wid >> 2;
    int row0 = m0 + warp_m*32 + (lane >> 2);
    int col0 = n0 + warp_n*64 + (lane & 3)*2;
    #pragma unroll
    for (int mf = 0; mf < 2; ++mf) {
        #pragma unroll
        for (int jf = 0; jf < 8; ++jf) {
            int cc = col0 + jf*8;
            float2 b2 = *(const float2*)(bias + cc);
            float2 o0, o1;
            o0.x = acc[mf][jf][0] + b2.x; o0.y = acc[mf][jf][1] + b2.y;
            o1.x = acc[mf][jf][2] + b2.x; o1.y = acc[mf][jf][3] + b2.y;
            *(float2*)(out + (size_t)(row0 + mf*16    )*DD + cc) = o0;
            *(float2*)(out + (size_t)(row0 + mf*16 + 8)*DD + cc) = o1;
        }
    }
}

// ---------------------------------------------------------------------------
// Kernel 4: cos GEMM (HMMA, single bf16 term) + IoU epilogue -> valid lists.
// bf16 cos error ~1e-4; any pair with |cos-0.2|<2e-3 is rechecked in exact fp32.
// ---------------------------------------------------------------------------
__global__ void __launch_bounds__(256) mask_tc_kernel(
    const float* __restrict__ query, const float* __restrict__ segments)
{
    extern __shared__ char dynsmem[];
    int b = blockIdx.z;
    int i0 = blockIdx.y * 128, j0 = blockIdx.x * 128;

    float acc[2][8][4];
    #pragma unroll
    for (int a = 0; a < 2; ++a)
        #pragma unroll
        for (int bb = 0; bb < 8; ++bb)
            #pragma unroll
            for (int c = 0; c < 4; ++c) acc[a][bb][c] = 0.f;

    hmma_mainloop<false>(dynsmem,
        g_hhi + (size_t)(b*LQ + i0) * DD, nullptr,
        g_hhi + (size_t)(b*LQ + j0) * DD, nullptr, acc);

    int lane = threadIdx.x & 31, wid = threadIdx.x >> 5;
    int warp_m = wid & 3, warp_n = wid >> 2;
    const float* seg = segments + (size_t)b * LQ * 2;

    int   gi[4], rid[4];
    float ni[4], si[4], ei[4], li[4];
    #pragma unroll
    for (int t = 0; t < 4; ++t) {
        int r = i0 + warp_m*32 + (lane >> 2) + (t >> 1)*16 + (t & 1)*8;
        gi[t] = r; rid[t] = b*LQ + r;
        ni[t] = g_invn[rid[t]];
        float cc = seg[r*2], ll = seg[r*2+1];
        si[t] = cc - ll*0.5f; ei[t] = cc + ll*0.5f; li[t] = ll;
    }

    #pragma unroll
    for (int jf = 0; jf < 8; ++jf) {
        #pragma unroll
        for (int c2 = 0; c2 < 2; ++c2) {
            int gj = j0 + warp_n*64 + jf*8 + (lane & 3)*2 + c2;
            float nj = g_invn[b*LQ + gj];
            float cj = seg[gj*2], lj = seg[gj*2+1];
            float sj = cj - lj*0.5f, ej = cj + lj*0.5f;
            #pragma unroll
            for (int t = 0; t < 4; ++t) {
                float cosv = acc[t >> 1][jf][(t & 1)*2 + c2] * ni[t] * nj;
                if (fabsf(cosv - 0.2f) < 2e-3f) {
                    // exact fp32 recheck (expected ~10 pairs over the whole batch)
                    const float* hp = query + (size_t)gi[t]*(BZ*DD) + (size_t)b*DD;
                    const float* hq = query + (size_t)gj   *(BZ*DD) + (size_t)b*DD;
                    float d = 0.f;
                    for (int k = 0; k < DD; ++k) d += hp[k] * hq[k];
                    cosv = d * ni[t] * nj;
                }
                float inter = fmaxf(fminf(ei[t], ej) - fmaxf(si[t], sj), 0.f);
                float uni   = (li[t] + lj) - inter;
                float iou   = inter / uni;
                bool valid = ((iou <= 0.2f) || (gi[t] == gj)) && (cosv > 0.2f);
                if (valid) {
                    int p = atomicAdd(&g_cnt[rid[t]], 1);
                    g_idx[((size_t)rid[t] << 10) + p] = gj;
                }
            }
        }
    }
}

// ---------------------------------------------------------------------------
// Kernel 5: sparse masked attention + residual
// ---------------------------------------------------------------------------
__global__ void __launch_bounds__(256) sattn_kernel(
    const float* __restrict__ query, float* __restrict__ out)
{
    __shared__ float sc[NH][LQ];

    int row = blockIdx.x;
    int b = row >> 10, i = row & 1023;
    int h = threadIdx.x >> 5, lane = threadIdx.x & 31;

    int c = g_cnt[row];
    const int* idx = g_idx + ((size_t)row << 10);

    const float* Qr = g_Q + (size_t)row * DD + h*DH;
    float2 q = *(const float2*)(Qr + lane*2);

    for (int t = 0; t < c; ++t) {
        int j = idx[t];
        const float* Kr = g_K + (size_t)(b*LQ + j) * DD + h*DH;
        float2 k = *(const float2*)(Kr + lane*2);
        float s = q.x*k.x + q.y*k.y;
        #pragma unroll
        for (int o = 16; o > 0; o >>= 1) s += __shfl_xor_sync(0xffffffffu, s, o);
        if (lane == 0) sc[h][t] = s * 0.125f;
    }
    __syncwarp();

    float m = -1e30f;
    for (int t = lane; t < c; t += 32) m = fmaxf(m, sc[h][t]);
    #pragma unroll
    for (int o = 16; o > 0; o >>= 1) m = fmaxf(m, __shfl_xor_sync(0xffffffffu, m, o));
    float l = 0.f;
    for (int t = lane; t < c; t += 32) {
        float p = expf(sc[h][t] - m);
        sc[h][t] = p;
        l += p;
    }
    #pragma unroll
    for (int o = 16; o > 0; o >>= 1) l += __shfl_xor_sync(0xffffffffu, l, o);
    __syncwarp();

    float o0 = 0.f, o1 = 0.f;
    for (int t = 0; t < c; ++t) {
        int j = idx[t];
        float p = sc[h][t];
        const float* Vr = g_V + (size_t)(b*LQ + j) * DD + h*DH;
        float2 v = *(const float2*)(Vr + lane*2);
        o0 += p * v.x;
        o1 += p * v.y;
    }
    float invl = 1.f / l;

    size_t off = (size_t)i*(BZ*DD) + (size_t)b*DD + h*DH + lane*2;
    float2 rv = *(const float2*)(query + off);
    float2 ov;
    ov.x = o0*invl + rv.x;
    ov.y = o1*invl + rv.y;
    *(float2*)(out + off) = ov;
}

// ---------------------------------------------------------------------------
extern "C" void kernel_launch(void* const* d_in, const int* in_sizes, int n_in,
                              void* d_out, int out_size)
{
    const float* query    = (const float*)d_in[0];
    const float* segments = (const float*)d_in[1];
    const float* Wq = (const float*)d_in[2];
    const float* bq = (const float*)d_in[3];
    const float* Wk = (const float*)d_in[4];
    const float* bk = (const float*)d_in[5];
    const float* Wv = (const float*)d_in[6];
    const float* bv = (const float*)d_in[7];
    float* out = (float*)d_out;

    cudaFuncSetAttribute(qkv_tc_kernel,  cudaFuncAttributeMaxDynamicSharedMemorySize, SMEM_QKV);
    cudaFuncSetAttribute(mask_tc_kernel, cudaFuncAttributeMaxDynamicSharedMemorySize, SMEM_MASK);

    norms_kernel  <<<MTOT/8, 256>>>(query);
    convert_kernel<<<(1048576 + 196608 + 255)/256, 256>>>(query, Wq, Wk, Wv);
    qkv_tc_kernel <<<dim3(DD/128, MTOT/128, 3), 256, SMEM_QKV>>>(bq, bk, bv);
    mask_tc_kernel<<<dim3(LQ/128, LQ/128, BZ), 256, SMEM_MASK>>>(query, segments);
    sattn_kernel  <<<MTOT, 256>>>(query, out);
}

// round 9
// speedup vs baseline: 9.6919x; 1.4052x over previous
#include <cuda_runtime.h>
#include <cuda_bf16.h>
#include <cuda_fp16.h>
#include <math.h>
#include <stdint.h>

#define LQ   1024
#define BZ   8
#define DD   512
#define NH   8
#define DH   64
#define MTOT (BZ*LQ)   // 8192

// GEMM tiling
#define LDSP        40                      // padded row length in elems (32 data + 8)
#define PLANE_BYTES (128*LDSP*2)            // 10240
#define NSTAGES     16                      // K=512 / BK=32
#define SMEM_SPLIT  (2*4*PLANE_BYTES)       // 81920 (dbl-buf, 4 planes)
#define SMEM_ONE    (2*2*PLANE_BYTES)       // 40960 (dbl-buf, 2 planes)

// ---------------- device scratch (allocation-free rule) ----------------
__device__ float g_Q[BZ*LQ*DD];
__device__ float g_K[BZ*LQ*DD];
__device__ float g_V[BZ*LQ*DD];
__device__ float g_invn[BZ*LQ];
__device__ int   g_cnt[BZ*LQ];
__device__ int   g_idx[(size_t)BZ*LQ*LQ];
__device__ __nv_bfloat16 g_hhi[MTOT*DD], g_hlo[MTOT*DD];   // h split (mask + V)
__device__ __half        g_hf16[MTOT*DD];                  // h fp16 (Q,K)
__device__ __half        g_Wf16[2*DD*DD];                  // Wq, Wk fp16
__device__ __nv_bfloat16 g_Wvhi[DD*DD], g_Wvlo[DD*DD];     // Wv split

// ---------------- helpers ----------------
__device__ __forceinline__ uint32_t smem_u32(const void* p) {
    uint32_t a;
    asm("{ .reg .u64 t; cvta.to.shared.u64 t, %1; cvt.u32.u64 %0, t; }" : "=r"(a) : "l"(p));
    return a;
}
__device__ __forceinline__ void cp_async16(uint32_t dst, const void* src) {
    asm volatile("cp.async.cg.shared.global [%0], [%1], 16;" :: "r"(dst), "l"(src) : "memory");
}
__device__ __forceinline__ void ldsm_x4(uint32_t* r, uint32_t addr) {
    asm volatile("ldmatrix.sync.aligned.m8n8.x4.shared.b16 {%0,%1,%2,%3}, [%4];"
                 : "=r"(r[0]), "=r"(r[1]), "=r"(r[2]), "=r"(r[3]) : "r"(addr));
}
__device__ __forceinline__ void ldsm_x2(uint32_t& r0, uint32_t& r1, uint32_t addr) {
    asm volatile("ldmatrix.sync.aligned.m8n8.x2.shared.b16 {%0,%1}, [%2];"
                 : "=r"(r0), "=r"(r1) : "r"(addr));
}
template<bool F16>
__device__ __forceinline__ void mma_any(float* c, const uint32_t* a, uint32_t b0, uint32_t b1) {
    if (F16)
        asm volatile(
            "mma.sync.aligned.m16n8k16.row.col.f32.f16.f16.f32 "
            "{%0,%1,%2,%3}, {%4,%5,%6,%7}, {%8,%9}, {%0,%1,%2,%3};"
            : "+f"(c[0]), "+f"(c[1]), "+f"(c[2]), "+f"(c[3])
            : "r"(a[0]), "r"(a[1]), "r"(a[2]), "r"(a[3]), "r"(b0), "r"(b1));
    else
        asm volatile(
            "mma.sync.aligned.m16n8k16.row.col.f32.bf16.bf16.f32 "
            "{%0,%1,%2,%3}, {%4,%5,%6,%7}, {%8,%9}, {%0,%1,%2,%3};"
            : "+f"(c[0]), "+f"(c[1]), "+f"(c[2]), "+f"(c[3])
            : "r"(a[0]), "r"(a[1]), "r"(a[2]), "r"(a[3]), "r"(b0), "r"(b1));
}

// ---------------------------------------------------------------------------
// Kernel 1: norms + counter init
// ---------------------------------------------------------------------------
__global__ void __launch_bounds__(256) norms_kernel(const float* __restrict__ query)
{
    int m    = blockIdx.x * 8 + (threadIdx.x >> 5);
    int lane = threadIdx.x & 31;
    if (threadIdx.x < 8) g_cnt[blockIdx.x * 8 + threadIdx.x] = 0;
    int b = m >> 10, i = m & 1023;
    const float* p = query + (size_t)i * (BZ*DD) + (size_t)b * DD;
    float ss = 0.f;
    #pragma unroll
    for (int j = 0; j < 16; ++j) { float v = p[lane + j*32]; ss += v*v; }
    #pragma unroll
    for (int o = 16; o > 0; o >>= 1) ss += __shfl_xor_sync(0xffffffffu, ss, o);
    if (lane == 0) g_invn[m] = 1.f / fmaxf(sqrtf(ss), 1e-8f);
}

// ---------------------------------------------------------------------------
// Kernel 2: convert h -> (bf16 hi/lo, fp16), Wq/Wk -> fp16, Wv -> bf16 hi/lo
// ---------------------------------------------------------------------------
__device__ __forceinline__ void split2(float x, __nv_bfloat16& h, __nv_bfloat16& l) {
    h = __float2bfloat16(x);
    l = __float2bfloat16(x - __bfloat162float(h));
}

__global__ void __launch_bounds__(256) convert_kernel(
    const float* __restrict__ query,
    const float* __restrict__ Wq, const float* __restrict__ Wk, const float* __restrict__ Wv)
{
    int idx = blockIdx.x * 256 + threadIdx.x;     // one float4
    if (idx < 1048576) {                          // h: 8192 rows x 128 float4
        int m = idx >> 7, k4 = (idx & 127) << 2;
        int b = m >> 10, i = m & 1023;
        float4 v = *(const float4*)(query + (size_t)i*(BZ*DD) + (size_t)b*DD + k4);
        size_t dst = (size_t)m * DD + k4;
        __nv_bfloat16 h0,l0,h1,l1,h2,l2,h3,l3;
        split2(v.x,h0,l0); split2(v.y,h1,l1); split2(v.z,h2,l2); split2(v.w,h3,l3);
        g_hhi[dst+0]=h0; g_hhi[dst+1]=h1; g_hhi[dst+2]=h2; g_hhi[dst+3]=h3;
        g_hlo[dst+0]=l0; g_hlo[dst+1]=l1; g_hlo[dst+2]=l2; g_hlo[dst+3]=l3;
        g_hf16[dst+0]=__float2half(v.x); g_hf16[dst+1]=__float2half(v.y);
        g_hf16[dst+2]=__float2half(v.z); g_hf16[dst+3]=__float2half(v.w);
    } else if (idx < 1048576 + 196608) {          // W: 3 x 65536 float4
        int e = idx - 1048576;
        int z = e >> 16, r = e & 65535;
        if (z < 2) {
            const float* W = (z == 0) ? Wq : Wk;
            float4 v = *(const float4*)(W + (size_t)r * 4);
            size_t dst = (size_t)z * (DD*DD) + (size_t)r * 4;
            g_Wf16[dst+0]=__float2half(v.x); g_Wf16[dst+1]=__float2half(v.y);
            g_Wf16[dst+2]=__float2half(v.z); g_Wf16[dst+3]=__float2half(v.w);
        } else {
            float4 v = *(const float4*)(Wv + (size_t)r * 4);
            size_t dst = (size_t)r * 4;
            __nv_bfloat16 h0,l0,h1,l1,h2,l2,h3,l3;
            split2(v.x,h0,l0); split2(v.y,h1,l1); split2(v.z,h2,l2); split2(v.w,h3,l3);
            g_Wvhi[dst+0]=h0; g_Wvhi[dst+1]=h1; g_Wvhi[dst+2]=h2; g_Wvhi[dst+3]=h3;
            g_Wvlo[dst+0]=l0; g_Wvlo[dst+1]=l1; g_Wvlo[dst+2]=l2; g_Wvlo[dst+3]=l3;
        }
    }
}

// ---------------------------------------------------------------------------
// HMMA mainloop. SPLIT: 3-term bf16 split (planes Ahi,Alo,Bhi,Blo).
// !SPLIT: single term (planes A,B) of type F16?fp16:bf16.
// Block 256 thr = 8 warps (4Mx2N), warp tile 32x64, BK=32, K=512, dbl-buffered.
// ---------------------------------------------------------------------------
template<bool SPLIT, bool F16>
__device__ __forceinline__ void hmma_mainloop(char* smem,
    const uint16_t* __restrict__ Ahi, const uint16_t* __restrict__ Alo,
    const uint16_t* __restrict__ Bhi, const uint16_t* __restrict__ Blo,
    float acc[2][8][4])
{
    constexpr int NP   = SPLIT ? 4 : 2;
    constexpr int NIT  = NP * 2;
    constexpr uint32_t STG = NP * PLANE_BYTES;
    constexpr uint32_t BPL = (SPLIT ? 2 : 1) * PLANE_BYTES;

    const uint16_t* gsrc[NP];
    gsrc[0] = Ahi;
    if (SPLIT) { gsrc[1] = Alo; gsrc[2] = Bhi; gsrc[3] = Blo; }
    else       { gsrc[1] = Bhi; }

    int tid = threadIdx.x, lane = tid & 31, wid = tid >> 5;
    int warp_m = wid & 3, warp_n = wid >> 2;
    uint32_t sbase = smem_u32(smem);

    int ca[NIT], crow[NIT], cch[NIT];
    #pragma unroll
    for (int it = 0; it < NIT; ++it) {
        int c = tid + it * 256;
        ca[it]   = c >> 9;
        crow[it] = (c >> 2) & 127;
        cch[it]  = c & 3;
    }

    int r8 = lane & 7, g = lane >> 3;
    uint32_t aoff[2];
    #pragma unroll
    for (int mf = 0; mf < 2; ++mf)
        aoff[mf] = ((warp_m*32 + mf*16 + r8 + (g & 1)*8) * LDSP + ((g >> 1) & 1)*8) * 2;
    int qb = lane & 15, rb = qb & 7, gb = qb >> 3;
    uint32_t boff[8];
    #pragma unroll
    for (int jf = 0; jf < 8; ++jf)
        boff[jf] = ((warp_n*64 + jf*8 + rb) * LDSP + gb*8) * 2;

    #pragma unroll
    for (int it = 0; it < NIT; ++it) {
        uint32_t dst = sbase + ca[it]*PLANE_BYTES + crow[it]*(LDSP*2) + cch[it]*16;
        cp_async16(dst, gsrc[ca[it]] + (size_t)crow[it]*DD + cch[it]*8);
    }
    asm volatile("cp.async.commit_group;" ::: "memory");

    for (int s = 0; s < NSTAGES; ++s) {
        if (s + 1 < NSTAGES) {
            int k0 = (s + 1) * 32;
            uint32_t dbase = sbase + ((s + 1) & 1) * STG;
            #pragma unroll
            for (int it = 0; it < NIT; ++it) {
                uint32_t dst = dbase + ca[it]*PLANE_BYTES + crow[it]*(LDSP*2) + cch[it]*16;
                cp_async16(dst, gsrc[ca[it]] + (size_t)crow[it]*DD + k0 + cch[it]*8);
            }
            asm volatile("cp.async.commit_group;" ::: "memory");
            asm volatile("cp.async.wait_group 1;" ::: "memory");
        } else {
            asm volatile("cp.async.wait_group 0;" ::: "memory");
        }
        __syncthreads();

        uint32_t st = sbase + (s & 1) * STG;
        #pragma unroll
        for (int ks = 0; ks < 2; ++ks) {
            uint32_t kofs = ks * 32;
            uint32_t ah[2][4], al[2][4];
            #pragma unroll
            for (int mf = 0; mf < 2; ++mf) {
                ldsm_x4(ah[mf], st + aoff[mf] + kofs);
                if (SPLIT) ldsm_x4(al[mf], st + PLANE_BYTES + aoff[mf] + kofs);
            }
            #pragma unroll
            for (int half = 0; half < 2; ++half) {
                uint32_t bh[4][2], bl[4][2];
                #pragma unroll
                for (int j = 0; j < 4; ++j) {
                    ldsm_x2(bh[j][0], bh[j][1], st + BPL + boff[half*4+j] + kofs);
                    if (SPLIT)
                        ldsm_x2(bl[j][0], bl[j][1], st + 3*PLANE_BYTES + boff[half*4+j] + kofs);
                }
                #pragma unroll
                for (int j = 0; j < 4; ++j)
                    #pragma unroll
                    for (int mf = 0; mf < 2; ++mf)
                        mma_any<F16>(acc[mf][half*4+j], ah[mf], bh[j][0], bh[j][1]);
                if (SPLIT) {
                    #pragma unroll
                    for (int j = 0; j < 4; ++j)
                        #pragma unroll
                        for (int mf = 0; mf < 2; ++mf)
                            mma_any<F16>(acc[mf][half*4+j], ah[mf], bl[j][0], bl[j][1]);
                    #pragma unroll
                    for (int j = 0; j < 4; ++j)
                        #pragma unroll
                        for (int mf = 0; mf < 2; ++mf)
                            mma_any<F16>(acc[mf][half*4+j], al[mf], bh[j][0], bh[j][1]);
                }
            }
        }
        __syncthreads();
    }
}

// shared epilogue: +bias, store fp32
__device__ __forceinline__ void proj_epilogue(float acc[2][8][4],
    const float* __restrict__ bias, float* __restrict__ out, int m0, int n0)
{
    int lane = threadIdx.x & 31, wid = threadIdx.x >> 5;
    int warp_m = wid & 3, warp_n = wid >> 2;
    int row0 = m0 + warp_m*32 + (lane >> 2);
    int col0 = n0 + warp_n*64 + (lane & 3)*2;
    #pragma unroll
    for (int mf = 0; mf < 2; ++mf) {
        #pragma unroll
        for (int jf = 0; jf < 8; ++jf) {
            int cc = col0 + jf*8;
            float2 b2 = *(const float2*)(bias + cc);
            float2 o0, o1;
            o0.x = acc[mf][jf][0] + b2.x; o0.y = acc[mf][jf][1] + b2.y;
            o1.x = acc[mf][jf][2] + b2.x; o1.y = acc[mf][jf][3] + b2.y;
            *(float2*)(out + (size_t)(row0 + mf*16    )*DD + cc) = o0;
            *(float2*)(out + (size_t)(row0 + mf*16 + 8)*DD + cc) = o1;
        }
    }
}

// ---------------------------------------------------------------------------
// Kernel 3a: Q,K projections — single-term fp16 HMMA
// ---------------------------------------------------------------------------
__global__ void __launch_bounds__(256) qk_tc_kernel(
    const float* __restrict__ bq, const float* __restrict__ bk)
{
    extern __shared__ char dynsmem[];
    int z = blockIdx.z;
    int m0 = blockIdx.y * 128, n0 = blockIdx.x * 128;
    const float* bias = (z == 0) ? bq : bk;
    float* out = (z == 0) ? g_Q : g_K;

    float acc[2][8][4];
    #pragma unroll
    for (int a = 0; a < 2; ++a)
        #pragma unroll
        for (int b = 0; b < 8; ++b)
            #pragma unroll
            for (int c = 0; c < 4; ++c) acc[a][b][c] = 0.f;

    hmma_mainloop<false, true>(dynsmem,
        (const uint16_t*)(g_hf16 + (size_t)m0 * DD), nullptr,
        (const uint16_t*)(g_Wf16 + (size_t)z*(DD*DD) + (size_t)n0 * DD), nullptr, acc);

    proj_epilogue(acc, bias, out, m0, n0);
}

// ---------------------------------------------------------------------------
// Kernel 3b: V projection — 3-term bf16 split HMMA
// ---------------------------------------------------------------------------
__global__ void __launch_bounds__(256) v_tc_kernel(const float* __restrict__ bv)
{
    extern __shared__ char dynsmem[];
    int m0 = blockIdx.y * 128, n0 = blockIdx.x * 128;

    float acc[2][8][4];
    #pragma unroll
    for (int a = 0; a < 2; ++a)
        #pragma unroll
        for (int b = 0; b < 8; ++b)
            #pragma unroll
            for (int c = 0; c < 4; ++c) acc[a][b][c] = 0.f;

    hmma_mainloop<true, false>(dynsmem,
        (const uint16_t*)(g_hhi + (size_t)m0 * DD),
        (const uint16_t*)(g_hlo + (size_t)m0 * DD),
        (const uint16_t*)(g_Wvhi + (size_t)n0 * DD),
        (const uint16_t*)(g_Wvlo + (size_t)n0 * DD), acc);

    proj_epilogue(acc, bv, g_V, m0, n0);
}

// ---------------------------------------------------------------------------
// Kernel 4: cos GEMM (single bf16 term) on UPPER-TRIANGULAR block pairs only
// (valid() is symmetric); off-diagonal blocks mirror-append to both rows.
// bf16 cos error ~1e-4; |cos-0.2|<2e-3 rechecked in exact fp32.
// ---------------------------------------------------------------------------
__global__ void __launch_bounds__(256) mask_tc_kernel(
    const float* __restrict__ query, const float* __restrict__ segments)
{
    extern __shared__ char dynsmem[];
    int b = blockIdx.z;
    // map blockIdx.x (0..35) -> (bi, bj) with bj >= bi over 8x8 blocks
    int t = blockIdx.x, bi = 0;
    while (t >= 8 - bi) { t -= 8 - bi; ++bi; }
    int bj = bi + t;
    int i0 = bi * 128, j0 = bj * 128;
    bool mirror = (bi != bj);

    float acc[2][8][4];
    #pragma unroll
    for (int a = 0; a < 2; ++a)
        #pragma unroll
        for (int bb = 0; bb < 8; ++bb)
            #pragma unroll
            for (int c = 0; c < 4; ++c) acc[a][bb][c] = 0.f;

    hmma_mainloop<false, false>(dynsmem,
        (const uint16_t*)(g_hhi + (size_t)(b*LQ + i0) * DD), nullptr,
        (const uint16_t*)(g_hhi + (size_t)(b*LQ + j0) * DD), nullptr, acc);

    int lane = threadIdx.x & 31, wid = threadIdx.x >> 5;
    int warp_m = wid & 3, warp_n = wid >> 2;
    const float* seg = segments + (size_t)b * LQ * 2;

    int   gi[4], rid[4];
    float ni[4], si[4], ei[4], li[4];
    #pragma unroll
    for (int u = 0; u < 4; ++u) {
        int r = i0 + warp_m*32 + (lane >> 2) + (u >> 1)*16 + (u & 1)*8;
        gi[u] = r; rid[u] = b*LQ + r;
        ni[u] = g_invn[rid[u]];
        float cc = seg[r*2], ll = seg[r*2+1];
        si[u] = cc - ll*0.5f; ei[u] = cc + ll*0.5f; li[u] = ll;
    }

    #pragma unroll
    for (int jf = 0; jf < 8; ++jf) {
        #pragma unroll
        for (int c2 = 0; c2 < 2; ++c2) {
            int gj = j0 + warp_n*64 + jf*8 + (lane & 3)*2 + c2;
            float nj = g_invn[b*LQ + gj];
            float cj = seg[gj*2], lj = seg[gj*2+1];
            float sj = cj - lj*0.5f, ej = cj + lj*0.5f;
            #pragma unroll
            for (int u = 0; u < 4; ++u) {
                float cosv = acc[u >> 1][jf][(u & 1)*2 + c2] * ni[u] * nj;
                if (fabsf(cosv - 0.2f) < 2e-3f) {
                    // exact fp32 recheck (expected ~few pairs in the whole batch)
                    const float* hp = query + (size_t)gi[u]*(BZ*DD) + (size_t)b*DD;
                    const float* hq = query + (size_t)gj   *(BZ*DD) + (size_t)b*DD;
                    float d = 0.f;
                    for (int k = 0; k < DD; ++k) d += hp[k] * hq[k];
                    cosv = d * ni[u] * nj;
                }
                float inter = fmaxf(fminf(ei[u], ej) - fmaxf(si[u], sj), 0.f);
                float uni   = (li[u] + lj) - inter;
                float iou   = inter / uni;
                bool valid = ((iou <= 0.2f) || (gi[u] == gj)) && (cosv > 0.2f);
                if (valid) {
                    int p = atomicAdd(&g_cnt[rid[u]], 1);
                    g_idx[((size_t)rid[u] << 10) + p] = gj;
                    if (mirror) {
                        int rj = b*LQ + gj;
                        int p2 = atomicAdd(&g_cnt[rj], 1);
                        g_idx[((size_t)rj << 10) + p2] = gi[u];
                    }
                }
            }
        }
    }
}

// ---------------------------------------------------------------------------
// Kernel 5: sparse masked attention + residual
// ---------------------------------------------------------------------------
__global__ void __launch_bounds__(256) sattn_kernel(
    const float* __restrict__ query, float* __restrict__ out)
{
    __shared__ float sc[NH][LQ];

    int row = blockIdx.x;
    int b = row >> 10, i = row & 1023;
    int h = threadIdx.x >> 5, lane = threadIdx.x & 31;

    int c = g_cnt[row];
    const int* idx = g_idx + ((size_t)row << 10);

    const float* Qr = g_Q + (size_t)row * DD + h*DH;
    float2 q = *(const float2*)(Qr + lane*2);

    for (int t = 0; t < c; ++t) {
        int j = idx[t];
        const float* Kr = g_K + (size_t)(b*LQ + j) * DD + h*DH;
        float2 k = *(const float2*)(Kr + lane*2);
        float s = q.x*k.x + q.y*k.y;
        #pragma unroll
        for (int o = 16; o > 0; o >>= 1) s += __shfl_xor_sync(0xffffffffu, s, o);
        if (lane == 0) sc[h][t] = s * 0.125f;
    }
    __syncwarp();

    float m = -1e30f;
    for (int t = lane; t < c; t += 32) m = fmaxf(m, sc[h][t]);
    #pragma unroll
    for (int o = 16; o > 0; o >>= 1) m = fmaxf(m, __shfl_xor_sync(0xffffffffu, m, o));
    float l = 0.f;
    for (int t = lane; t < c; t += 32) {
        float p = expf(sc[h][t] - m);
        sc[h][t] = p;
        l += p;
    }
    #pragma unroll
    for (int o = 16; o > 0; o >>= 1) l += __shfl_xor_sync(0xffffffffu, l, o);
    __syncwarp();

    float o0 = 0.f, o1 = 0.f;
    for (int t = 0; t < c; ++t) {
        int j = idx[t];
        float p = sc[h][t];
        const float* Vr = g_V + (size_t)(b*LQ + j) * DD + h*DH;
        float2 v = *(const float2*)(Vr + lane*2);
        o0 += p * v.x;
        o1 += p * v.y;
    }
    float invl = 1.f / l;

    size_t off = (size_t)i*(BZ*DD) + (size_t)b*DD + h*DH + lane*2;
    float2 rv = *(const float2*)(query + off);
    float2 ov;
    ov.x = o0*invl + rv.x;
    ov.y = o1*invl + rv.y;
    *(float2*)(out + off) = ov;
}

// ---------------------------------------------------------------------------
extern "C" void kernel_launch(void* const* d_in, const int* in_sizes, int n_in,
                              void* d_out, int out_size)
{
    const float* query    = (const float*)d_in[0];
    const float* segments = (const float*)d_in[1];
    const float* Wq = (const float*)d_in[2];
    const float* bq = (const float*)d_in[3];
    const float* Wk = (const float*)d_in[4];
    const float* bk = (const float*)d_in[5];
    const float* Wv = (const float*)d_in[6];
    const float* bv = (const float*)d_in[7];
    float* out = (float*)d_out;

    cudaFuncSetAttribute(qk_tc_kernel,   cudaFuncAttributeMaxDynamicSharedMemorySize, SMEM_ONE);
    cudaFuncSetAttribute(v_tc_kernel,    cudaFuncAttributeMaxDynamicSharedMemorySize, SMEM_SPLIT);
    cudaFuncSetAttribute(mask_tc_kernel, cudaFuncAttributeMaxDynamicSharedMemorySize, SMEM_ONE);

    norms_kernel  <<<MTOT/8, 256>>>(query);
    convert_kernel<<<(1048576 + 196608 + 255)/256, 256>>>(query, Wq, Wk, Wv);
    qk_tc_kernel  <<<dim3(DD/128, MTOT/128, 2), 256, SMEM_ONE>>>(bq, bk);
    v_tc_kernel   <<<dim3(DD/128, MTOT/128), 256, SMEM_SPLIT>>>(bv);
    mask_tc_kernel<<<dim3(36, 1, BZ), 256, SMEM_ONE>>>(query, segments);
    sattn_kernel  <<<MTOT, 256>>>(query, out);
}

// round 10
// speedup vs baseline: 14.3230x; 1.4778x over previous
#include <cuda_runtime.h>
#include <cuda_fp16.h>
#include <math.h>
#include <stdint.h>

#define LQ   1024
#define BZ   8
#define DD   512
#define NH   8
#define DH   64
#define MTOT (BZ*LQ)   // 8192

// GEMM tiling: 128x128 tile, BK=32, single-term fp16, 4-deep cp.async pipeline
#define LDSP        40                      // padded row length in elems (32 data + 8)
#define PLANE_BYTES (128*LDSP*2)            // 10240
#define NSTAGES     16                      // K=512 / BK=32
#define PIPE        4
#define STG         (2*PLANE_BYTES)         // 20480 per stage (A + B planes)
#define SMEM_PIPE   (PIPE*STG)              // 81920

// ---------------- device scratch (allocation-free rule) ----------------
__device__ float g_Q[BZ*LQ*DD];
__device__ float g_K[BZ*LQ*DD];
__device__ float g_V[BZ*LQ*DD];
__device__ float g_invn[BZ*LQ];
__device__ int   g_cnt[BZ*LQ];
__device__ int   g_idx[(size_t)BZ*LQ*LQ];
__device__ __half g_hf16[MTOT*DD];          // h fp16 (all GEMMs)
__device__ __half g_Wf16[3*DD*DD];          // Wq, Wk, Wv fp16

// ---------------- helpers ----------------
__device__ __forceinline__ uint32_t smem_u32(const void* p) {
    uint32_t a;
    asm("{ .reg .u64 t; cvta.to.shared.u64 t, %1; cvt.u32.u64 %0, t; }" : "=r"(a) : "l"(p));
    return a;
}
__device__ __forceinline__ void cp_async16(uint32_t dst, const void* src) {
    asm volatile("cp.async.cg.shared.global [%0], [%1], 16;" :: "r"(dst), "l"(src) : "memory");
}
__device__ __forceinline__ void ldsm_x4(uint32_t* r, uint32_t addr) {
    asm volatile("ldmatrix.sync.aligned.m8n8.x4.shared.b16 {%0,%1,%2,%3}, [%4];"
                 : "=r"(r[0]), "=r"(r[1]), "=r"(r[2]), "=r"(r[3]) : "r"(addr));
}
__device__ __forceinline__ void ldsm_x2(uint32_t& r0, uint32_t& r1, uint32_t addr) {
    asm volatile("ldmatrix.sync.aligned.m8n8.x2.shared.b16 {%0,%1}, [%2];"
                 : "=r"(r0), "=r"(r1) : "r"(addr));
}
__device__ __forceinline__ void mma_f16(float* c, const uint32_t* a, uint32_t b0, uint32_t b1) {
    asm volatile(
        "mma.sync.aligned.m16n8k16.row.col.f32.f16.f16.f32 "
        "{%0,%1,%2,%3}, {%4,%5,%6,%7}, {%8,%9}, {%0,%1,%2,%3};"
        : "+f"(c[0]), "+f"(c[1]), "+f"(c[2]), "+f"(c[3])
        : "r"(a[0]), "r"(a[1]), "r"(a[2]), "r"(a[3]), "r"(b0), "r"(b1));
}

// ---------------------------------------------------------------------------
// Kernel 1: norms + counter init
// ---------------------------------------------------------------------------
__global__ void __launch_bounds__(256) norms_kernel(const float* __restrict__ query)
{
    int m    = blockIdx.x * 8 + (threadIdx.x >> 5);
    int lane = threadIdx.x & 31;
    if (threadIdx.x < 8) g_cnt[blockIdx.x * 8 + threadIdx.x] = 0;
    int b = m >> 10, i = m & 1023;
    const float* p = query + (size_t)i * (BZ*DD) + (size_t)b * DD;
    float ss = 0.f;
    #pragma unroll
    for (int j = 0; j < 16; ++j) { float v = p[lane + j*32]; ss += v*v; }
    #pragma unroll
    for (int o = 16; o > 0; o >>= 1) ss += __shfl_xor_sync(0xffffffffu, ss, o);
    if (lane == 0) g_invn[m] = 1.f / fmaxf(sqrtf(ss), 1e-8f);
}

// ---------------------------------------------------------------------------
// Kernel 2: convert h (transposed to [b*LQ+i][d]) and Wq/Wk/Wv to fp16
// ---------------------------------------------------------------------------
__global__ void __launch_bounds__(256) convert_kernel(
    const float* __restrict__ query,
    const float* __restrict__ Wq, const float* __restrict__ Wk, const float* __restrict__ Wv)
{
    int idx = blockIdx.x * 256 + threadIdx.x;     // one float4
    if (idx < 1048576) {                          // h: 8192 rows x 128 float4
        int m = idx >> 7, k4 = (idx & 127) << 2;
        int b = m >> 10, i = m & 1023;
        float4 v = *(const float4*)(query + (size_t)i*(BZ*DD) + (size_t)b*DD + k4);
        __half2* d = (__half2*)(g_hf16 + (size_t)m * DD + k4);
        d[0] = __floats2half2_rn(v.x, v.y);
        d[1] = __floats2half2_rn(v.z, v.w);
    } else if (idx < 1048576 + 196608) {          // W: 3 x 65536 float4
        int e = idx - 1048576;
        int z = e >> 16, r = e & 65535;
        const float* W = (z == 0) ? Wq : ((z == 1) ? Wk : Wv);
        float4 v = *(const float4*)(W + (size_t)r * 4);
        __half2* d = (__half2*)(g_Wf16 + (size_t)z * (DD*DD) + (size_t)r * 4);
        d[0] = __floats2half2_rn(v.x, v.y);
        d[1] = __floats2half2_rn(v.z, v.w);
    }
}

// ---------------------------------------------------------------------------
// fp16 HMMA mainloop: acc[2][8][4] += A[128xK] * B[128xK]^T, K=512.
// 8 warps (4Mx2N), warp tile 32x64, BK=32, 4-deep cp.async pipeline.
// ---------------------------------------------------------------------------
__device__ __forceinline__ void hmma_loop(char* smem,
    const __half* __restrict__ A, const __half* __restrict__ B, float acc[2][8][4])
{
    const __half* gsrc[2] = { A, B };
    int tid = threadIdx.x, lane = tid & 31, wid = tid >> 5;
    int warp_m = wid & 3, warp_n = wid >> 2;
    uint32_t sbase = smem_u32(smem);

    // per-thread cp.async coords (4 chunks of 16B per stage)
    int ca[4], crow[4], cch[4];
    #pragma unroll
    for (int it = 0; it < 4; ++it) {
        int c = tid + it * 256;            // 0..1023
        ca[it]   = c >> 9;                 // 0 = A plane, 1 = B plane
        crow[it] = (c >> 2) & 127;
        cch[it]  = c & 3;
    }

    // ldmatrix base offsets (bytes, within a plane)
    int r8 = lane & 7, g = lane >> 3;
    uint32_t aoff[2];
    #pragma unroll
    for (int mf = 0; mf < 2; ++mf)
        aoff[mf] = ((warp_m*32 + mf*16 + r8 + (g & 1)*8) * LDSP + ((g >> 1) & 1)*8) * 2;
    int qb = lane & 15, rb = qb & 7, gb = qb >> 3;
    uint32_t boff[8];
    #pragma unroll
    for (int jf = 0; jf < 8; ++jf)
        boff[jf] = ((warp_n*64 + jf*8 + rb) * LDSP + gb*8) * 2;

    // preload stages 0..2
    #pragma unroll
    for (int ps = 0; ps < PIPE-1; ++ps) {
        uint32_t dbase = sbase + ps * STG;
        int k0 = ps * 32;
        #pragma unroll
        for (int it = 0; it < 4; ++it) {
            uint32_t dst = dbase + ca[it]*PLANE_BYTES + crow[it]*(LDSP*2) + cch[it]*16;
            cp_async16(dst, gsrc[ca[it]] + (size_t)crow[it]*DD + k0 + cch[it]*8);
        }
        asm volatile("cp.async.commit_group;" ::: "memory");
    }

    for (int s = 0; s < NSTAGES; ++s) {
        asm volatile("cp.async.wait_group 2;" ::: "memory");
        __syncthreads();

        // issue stage s+3 (or empty commit to keep group accounting uniform)
        if (s + PIPE - 1 < NSTAGES) {
            int sn = s + PIPE - 1;
            uint32_t dbase = sbase + (sn & (PIPE-1)) * STG;
            int k0 = sn * 32;
            #pragma unroll
            for (int it = 0; it < 4; ++it) {
                uint32_t dst = dbase + ca[it]*PLANE_BYTES + crow[it]*(LDSP*2) + cch[it]*16;
                cp_async16(dst, gsrc[ca[it]] + (size_t)crow[it]*DD + k0 + cch[it]*8);
            }
        }
        asm volatile("cp.async.commit_group;" ::: "memory");

        uint32_t st = sbase + (s & (PIPE-1)) * STG;
        #pragma unroll
        for (int ks = 0; ks < 2; ++ks) {
            uint32_t kofs = ks * 32;
            uint32_t ah[2][4];
            #pragma unroll
            for (int mf = 0; mf < 2; ++mf)
                ldsm_x4(ah[mf], st + aoff[mf] + kofs);
            #pragma unroll
            for (int half = 0; half < 2; ++half) {
                uint32_t bh[4][2];
                #pragma unroll
                for (int j = 0; j < 4; ++j)
                    ldsm_x2(bh[j][0], bh[j][1], st + PLANE_BYTES + boff[half*4+j] + kofs);
                #pragma unroll
                for (int j = 0; j < 4; ++j)
                    #pragma unroll
                    for (int mf = 0; mf < 2; ++mf)
                        mma_f16(acc[mf][half*4+j], ah[mf], bh[j][0], bh[j][1]);
            }
        }
    }
}

// ---------------------------------------------------------------------------
// Kernel 3: QKV projections — single-term fp16 HMMA (z selects Q/K/V)
// ---------------------------------------------------------------------------
__global__ void __launch_bounds__(256, 2) qkv_tc_kernel(
    const float* __restrict__ bq, const float* __restrict__ bk, const float* __restrict__ bv)
{
    extern __shared__ char dynsmem[];
    int z = blockIdx.z;
    int m0 = blockIdx.y * 128, n0 = blockIdx.x * 128;
    const float* bias = (z == 0) ? bq : ((z == 1) ? bk : bv);
    float* out = (z == 0) ? g_Q : ((z == 1) ? g_K : g_V);

    float acc[2][8][4];
    #pragma unroll
    for (int a = 0; a < 2; ++a)
        #pragma unroll
        for (int b = 0; b < 8; ++b)
            #pragma unroll
            for (int c = 0; c < 4; ++c) acc[a][b][c] = 0.f;

    hmma_loop(dynsmem,
        g_hf16 + (size_t)m0 * DD,
        g_Wf16 + (size_t)z*(DD*DD) + (size_t)n0 * DD, acc);

    int lane = threadIdx.x & 31, wid = threadIdx.x >> 5;
    int warp_m = wid & 3, warp_n = wid >> 2;
    int row0 = m0 + warp_m*32 + (lane >> 2);
    int col0 = n0 + warp_n*64 + (lane & 3)*2;
    #pragma unroll
    for (int mf = 0; mf < 2; ++mf) {
        #pragma unroll
        for (int jf = 0; jf < 8; ++jf) {
            int cc = col0 + jf*8;
            float2 b2 = *(const float2*)(bias + cc);
            float2 o0, o1;
            o0.x = acc[mf][jf][0] + b2.x; o0.y = acc[mf][jf][1] + b2.y;
            o1.x = acc[mf][jf][2] + b2.x; o1.y = acc[mf][jf][3] + b2.y;
            *(float2*)(out + (size_t)(row0 + mf*16    )*DD + cc) = o0;
            *(float2*)(out + (size_t)(row0 + mf*16 + 8)*DD + cc) = o1;
        }
    }
}

// ---------------------------------------------------------------------------
// Kernel 4: cos GEMM (fp16 single term) on upper-triangular block pairs;
// off-diagonal blocks mirror-append. fp16 cos error ~4e-5; |cos-0.2|<2e-3
// rechecked in exact fp32.
// ---------------------------------------------------------------------------
__global__ void __launch_bounds__(256, 2) mask_tc_kernel(
    const float* __restrict__ query, const float* __restrict__ segments)
{
    extern __shared__ char dynsmem[];
    int b = blockIdx.z;
    int t = blockIdx.x, bi = 0;
    while (t >= 8 - bi) { t -= 8 - bi; ++bi; }
    int bj = bi + t;
    int i0 = bi * 128, j0 = bj * 128;
    bool mirror = (bi != bj);

    float acc[2][8][4];
    #pragma unroll
    for (int a = 0; a < 2; ++a)
        #pragma unroll
        for (int bb = 0; bb < 8; ++bb)
            #pragma unroll
            for (int c = 0; c < 4; ++c) acc[a][bb][c] = 0.f;

    hmma_loop(dynsmem,
        g_hf16 + (size_t)(b*LQ + i0) * DD,
        g_hf16 + (size_t)(b*LQ + j0) * DD, acc);

    int lane = threadIdx.x & 31, wid = threadIdx.x >> 5;
    int warp_m = wid & 3, warp_n = wid >> 2;
    const float* seg = segments + (size_t)b * LQ * 2;

    int   gi[4], rid[4];
    float ni[4], si[4], ei[4], li[4];
    #pragma unroll
    for (int u = 0; u < 4; ++u) {
        int r = i0 + warp_m*32 + (lane >> 2) + (u >> 1)*16 + (u & 1)*8;
        gi[u] = r; rid[u] = b*LQ + r;
        ni[u] = g_invn[rid[u]];
        float cc = seg[r*2], ll = seg[r*2+1];
        si[u] = cc - ll*0.5f; ei[u] = cc + ll*0.5f; li[u] = ll;
    }

    #pragma unroll
    for (int jf = 0; jf < 8; ++jf) {
        #pragma unroll
        for (int c2 = 0; c2 < 2; ++c2) {
            int gj = j0 + warp_n*64 + jf*8 + (lane & 3)*2 + c2;
            float nj = g_invn[b*LQ + gj];
            float cj = seg[gj*2], lj = seg[gj*2+1];
            float sj = cj - lj*0.5f, ej = cj + lj*0.5f;
            #pragma unroll
            for (int u = 0; u < 4; ++u) {
                float cosv = acc[u >> 1][jf][(u & 1)*2 + c2] * ni[u] * nj;
                if (fabsf(cosv - 0.2f) < 2e-3f) {
                    // exact fp32 recheck (rare)
                    const float* hp = query + (size_t)gi[u]*(BZ*DD) + (size_t)b*DD;
                    const float* hq = query + (size_t)gj   *(BZ*DD) + (size_t)b*DD;
                    float d = 0.f;
                    for (int k = 0; k < DD; ++k) d += hp[k] * hq[k];
                    cosv = d * ni[u] * nj;
                }
                float inter = fmaxf(fminf(ei[u], ej) - fmaxf(si[u], sj), 0.f);
                float uni   = (li[u] + lj) - inter;
                float iou   = inter / uni;
                bool valid = ((iou <= 0.2f) || (gi[u] == gj)) && (cosv > 0.2f);
                if (valid) {
                    int p = atomicAdd(&g_cnt[rid[u]], 1);
                    g_idx[((size_t)rid[u] << 10) + p] = gj;
                    if (mirror) {
                        int rj = b*LQ + gj;
                        int p2 = atomicAdd(&g_cnt[rj], 1);
                        g_idx[((size_t)rj << 10) + p2] = gi[u];
                    }
                }
            }
        }
    }
}

// ---------------------------------------------------------------------------
// Kernel 5: sparse masked attention + residual. Fast path for c==1 rows
// (softmax weight is exactly 1 -> out = V[j] + h; no scores needed).
// ---------------------------------------------------------------------------
__global__ void __launch_bounds__(256) sattn_kernel(
    const float* __restrict__ query, float* __restrict__ out)
{
    __shared__ float sc[NH][LQ];

    int row = blockIdx.x;
    int b = row >> 10, i = row & 1023;
    int c = g_cnt[row];
    const int* idx = g_idx + ((size_t)row << 10);

    if (c == 1) {
        int j = idx[0];
        int t = threadIdx.x;                       // 256 threads x float2
        const float* Vr = g_V + (size_t)(b*LQ + j) * DD;
        size_t off = (size_t)i*(BZ*DD) + (size_t)b*DD + t*2;
        float2 v = *(const float2*)(Vr + t*2);
        float2 r = *(const float2*)(query + off);
        float2 o; o.x = v.x + r.x; o.y = v.y + r.y;
        *(float2*)(out + off) = o;
        return;
    }

    int h = threadIdx.x >> 5, lane = threadIdx.x & 31;
    const float* Qr = g_Q + (size_t)row * DD + h*DH;
    float2 q = *(const float2*)(Qr + lane*2);

    for (int t = 0; t < c; ++t) {
        int j = idx[t];
        const float* Kr = g_K + (size_t)(b*LQ + j) * DD + h*DH;
        float2 k = *(const float2*)(Kr + lane*2);
        float s = q.x*k.x + q.y*k.y;
        #pragma unroll
        for (int o = 16; o > 0; o >>= 1) s += __shfl_xor_sync(0xffffffffu, s, o);
        if (lane == 0) sc[h][t] = s * 0.125f;
    }
    __syncwarp();

    float m = -1e30f;
    for (int t = lane; t < c; t += 32) m = fmaxf(m, sc[h][t]);
    #pragma unroll
    for (int o = 16; o > 0; o >>= 1) m = fmaxf(m, __shfl_xor_sync(0xffffffffu, m, o));
    float l = 0.f;
    for (int t = lane; t < c; t += 32) {
        float p = expf(sc[h][t] - m);
        sc[h][t] = p;
        l += p;
    }
    #pragma unroll
    for (int o = 16; o > 0; o >>= 1) l += __shfl_xor_sync(0xffffffffu, l, o);
    __syncwarp();

    float o0 = 0.f, o1 = 0.f;
    for (int t = 0; t < c; ++t) {
        int j = idx[t];
        float p = sc[h][t];
        const float* Vr = g_V + (size_t)(b*LQ + j) * DD + h*DH;
        float2 v = *(const float2*)(Vr + lane*2);
        o0 += p * v.x;
        o1 += p * v.y;
    }
    float invl = 1.f / l;

    size_t off = (size_t)i*(BZ*DD) + (size_t)b*DD + h*DH + lane*2;
    float2 rv = *(const float2*)(query + off);
    float2 ov;
    ov.x = o0*invl + rv.x;
    ov.y = o1*invl + rv.y;
    *(float2*)(out + off) = ov;
}

// ---------------------------------------------------------------------------
extern "C" void kernel_launch(void* const* d_in, const int* in_sizes, int n_in,
                              void* d_out, int out_size)
{
    const float* query    = (const float*)d_in[0];
    const float* segments = (const float*)d_in[1];
    const float* Wq = (const float*)d_in[2];
    const float* bq = (const float*)d_in[3];
    const float* Wk = (const float*)d_in[4];
    const float* bk = (const float*)d_in[5];
    const float* Wv = (const float*)d_in[6];
    const float* bv = (const float*)d_in[7];
    float* out = (float*)d_out;

    cudaFuncSetAttribute(qkv_tc_kernel,  cudaFuncAttributeMaxDynamicSharedMemorySize, SMEM_PIPE);
    cudaFuncSetAttribute(mask_tc_kernel, cudaFuncAttributeMaxDynamicSharedMemorySize, SMEM_PIPE);

    norms_kernel  <<<MTOT/8, 256>>>(query);
    convert_kernel<<<(1048576 + 196608 + 255)/256, 256>>>(query, Wq, Wk, Wv);
    qkv_tc_kernel <<<dim3(DD/128, MTOT/128, 3), 256, SMEM_PIPE>>>(bq, bk, bv);
    mask_tc_kernel<<<dim3(36, 1, BZ), 256, SMEM_PIPE>>>(query, segments);
    sattn_kernel  <<<MTOT, 256>>>(query, out);
}

// round 13
// speedup vs baseline: 17.9436x; 1.2528x over previous
#include <cuda_runtime.h>
#include <cuda_fp16.h>
#include <math.h>
#include <stdint.h>

#define LQ   1024
#define BZ   8
#define DD   512
#define NH   8
#define DH   64
#define MTOT (BZ*LQ)   // 8192

// GEMM tiling: 128x128 tile, BK=64, single-term fp16, 2-buffer cp.async pipeline
#define LDSP        72                      // halfs per row (64 data + 8 pad)
#define ROWB        (LDSP*2)                // 144 bytes
#define PLANE_BYTES (128*ROWB)              // 18432
#define STG         (2*PLANE_BYTES)         // 36864 per stage (A + B planes)
#define PIPE        2
#define SMEM_PIPE   (PIPE*STG)              // 73728
#define NSTAGES     8                       // K=512 / BK=64

// ---------------- device scratch (allocation-free rule) ----------------
__device__ float g_Q[BZ*LQ*DD];
__device__ float g_K[BZ*LQ*DD];
__device__ float g_V[BZ*LQ*DD];
__device__ float g_invn[BZ*LQ];
__device__ int   g_cnt[BZ*LQ];
__device__ int   g_idx[(size_t)BZ*LQ*LQ];
__device__ __half g_hf16[MTOT*DD];          // h fp16 (all GEMMs)
__device__ __half g_Wf16[3*DD*DD];          // Wq, Wk, Wv fp16

// ---------------- helpers ----------------
__device__ __forceinline__ uint32_t smem_u32(const void* p) {
    uint32_t a;
    asm("{ .reg .u64 t; cvta.to.shared.u64 t, %1; cvt.u32.u64 %0, t; }" : "=r"(a) : "l"(p));
    return a;
}
__device__ __forceinline__ void cp_async16(uint32_t dst, const void* src) {
    asm volatile("cp.async.cg.shared.global [%0], [%1], 16;" :: "r"(dst), "l"(src) : "memory");
}
__device__ __forceinline__ void ldsm_x4(uint32_t* r, uint32_t addr) {
    asm volatile("ldmatrix.sync.aligned.m8n8.x4.shared.b16 {%0,%1,%2,%3}, [%4];"
                 : "=r"(r[0]), "=r"(r[1]), "=r"(r[2]), "=r"(r[3]) : "r"(addr));
}
__device__ __forceinline__ void mma_f16(float* c, const uint32_t* a, uint32_t b0, uint32_t b1) {
    asm volatile(
        "mma.sync.aligned.m16n8k16.row.col.f32.f16.f16.f32 "
        "{%0,%1,%2,%3}, {%4,%5,%6,%7}, {%8,%9}, {%0,%1,%2,%3};"
        : "+f"(c[0]), "+f"(c[1]), "+f"(c[2]), "+f"(c[3])
        : "r"(a[0]), "r"(a[1]), "r"(a[2]), "r"(a[3]), "r"(b0), "r"(b1));
}

// ---------------------------------------------------------------------------
// Kernel 1: fused norms + counter init + h->fp16 + W->fp16
// blocks 0..1023: h rows (warp per row). blocks 1024..1791: W conversion.
// ---------------------------------------------------------------------------
__global__ void __launch_bounds__(256) prep_kernel(
    const float* __restrict__ query,
    const float* __restrict__ Wq, const float* __restrict__ Wk, const float* __restrict__ Wv)
{
    int bx = blockIdx.x, tid = threadIdx.x;
    if (bx < 1024) {
        int wid = tid >> 5, lane = tid & 31;
        int m = bx * 8 + wid;
        int b = m >> 10, i = m & 1023;
        if (tid < 8) g_cnt[bx * 8 + tid] = 0;
        const float4* p = (const float4*)(query + (size_t)i*(BZ*DD) + (size_t)b*DD);
        __half2* d = (__half2*)(g_hf16 + (size_t)m * DD);
        float ss = 0.f;
        #pragma unroll
        for (int j = 0; j < 4; ++j) {
            float4 v = p[lane + j*32];
            ss += v.x*v.x + v.y*v.y + v.z*v.z + v.w*v.w;
            d[(lane + j*32)*2 + 0] = __floats2half2_rn(v.x, v.y);
            d[(lane + j*32)*2 + 1] = __floats2half2_rn(v.z, v.w);
        }
        #pragma unroll
        for (int o = 16; o > 0; o >>= 1) ss += __shfl_xor_sync(0xffffffffu, ss, o);
        if (lane == 0) g_invn[m] = 1.f / fmaxf(sqrtf(ss), 1e-8f);
    } else {
        int e = (bx - 1024) * 256 + tid;          // 0..196607 float4s
        int z = e >> 16, r = e & 65535;
        const float* W = (z == 0) ? Wq : ((z == 1) ? Wk : Wv);
        float4 v = *(const float4*)(W + (size_t)r * 4);
        __half2* d = (__half2*)(g_Wf16 + (size_t)z * (DD*DD) + (size_t)r * 4);
        d[0] = __floats2half2_rn(v.x, v.y);
        d[1] = __floats2half2_rn(v.z, v.w);
    }
}

// ---------------------------------------------------------------------------
// fp16 HMMA mainloop: acc[2][8][4] += A[128xK] * B[128xK]^T, K=512.
// 8 warps (4Mx2N), warp tile 32x64, BK=64, 2-buffer pipeline,
// sync-before-issue (safe with 2 buffers), paired x4 ldmatrix for B.
// ---------------------------------------------------------------------------
__device__ __forceinline__ void hmma_loop(char* smem,
    const __half* __restrict__ A, const __half* __restrict__ B, float acc[2][8][4])
{
    const __half* gsrc[2] = { A, B };
    int tid = threadIdx.x, lane = tid & 31, wid = tid >> 5;
    int warp_m = wid & 3, warp_n = wid >> 2;
    uint32_t sbase = smem_u32(smem);

    // per-thread cp.async coords: 8 chunks of 16B per stage (2 planes x 4)
    int cpl[8], crow[8], cch[8];
    #pragma unroll
    for (int it = 0; it < 8; ++it) {
        int c = tid + it * 256;            // 0..2047
        cpl[it]  = c >> 10;                // 0 = A plane, 1 = B plane
        int idx  = c & 1023;
        crow[it] = idx >> 3;
        cch[it]  = idx & 7;
    }

    // ldmatrix base offsets (bytes, within a plane)
    int r8 = lane & 7, g = lane >> 3;
    uint32_t aoff[2];
    #pragma unroll
    for (int mf = 0; mf < 2; ++mf)
        aoff[mf] = (warp_m*32 + mf*16 + r8 + (g & 1)*8) * ROWB + ((g >> 1) & 1)*16;
    // paired B x4: groups -> (jsel, ksel)
    int jsel = (lane >> 4) & 1, ksel = (lane >> 3) & 1;
    uint32_t boff[4];
    #pragma unroll
    for (int jp = 0; jp < 4; ++jp)
        boff[jp] = (warp_n*64 + jp*16 + jsel*8 + r8) * ROWB + ksel*16;

    // preload stage 0
    #pragma unroll
    for (int it = 0; it < 8; ++it) {
        uint32_t dst = sbase + cpl[it]*PLANE_BYTES + crow[it]*ROWB + cch[it]*16;
        cp_async16(dst, gsrc[cpl[it]] + (size_t)crow[it]*DD + cch[it]*8);
    }
    asm volatile("cp.async.commit_group;" ::: "memory");

    for (int s = 0; s < NSTAGES; ++s) {
        asm volatile("cp.async.wait_group 0;" ::: "memory");   // stage s landed
        __syncthreads();                                        // all done with slot (s+1)&1
        if (s + 1 < NSTAGES) {
            int k0 = (s + 1) * 64;
            uint32_t dbase = sbase + ((s + 1) & 1) * STG;
            #pragma unroll
            for (int it = 0; it < 8; ++it) {
                uint32_t dst = dbase + cpl[it]*PLANE_BYTES + crow[it]*ROWB + cch[it]*16;
                cp_async16(dst, gsrc[cpl[it]] + (size_t)crow[it]*DD + k0 + cch[it]*8);
            }
            asm volatile("cp.async.commit_group;" ::: "memory");
        }

        uint32_t st = sbase + (s & 1) * STG;
        #pragma unroll
        for (int ks = 0; ks < 4; ++ks) {
            uint32_t kofs = ks * 32;                 // 16 halfs = 32 bytes
            uint32_t ah[2][4];
            #pragma unroll
            for (int mf = 0; mf < 2; ++mf)
                ldsm_x4(ah[mf], st + aoff[mf] + kofs);
            uint32_t bb[4][4];
            #pragma unroll
            for (int jp = 0; jp < 4; ++jp)
                ldsm_x4(bb[jp], st + PLANE_BYTES + boff[jp] + kofs);
            #pragma unroll
            for (int jp = 0; jp < 4; ++jp)
                #pragma unroll
                for (int hf = 0; hf < 2; ++hf)
                    #pragma unroll
                    for (int mf = 0; mf < 2; ++mf)
                        mma_f16(acc[mf][jp*2+hf], ah[mf], bb[jp][hf*2], bb[jp][hf*2+1]);
        }
    }
}

// ---------------------------------------------------------------------------
// Kernel 2: fused GEMM launch.
//  blocks [0,768):   QKV projection tiles (z = bx>>8)
//  blocks [768,1056): mask cos tiles (upper-triangular pairs + mirror)
// ---------------------------------------------------------------------------
__global__ void __launch_bounds__(256, 2) fused_gemm_kernel(
    const float* __restrict__ query, const float* __restrict__ segments,
    const float* __restrict__ bq, const float* __restrict__ bk, const float* __restrict__ bv)
{
    extern __shared__ char dynsmem[];
    int bx = blockIdx.x;
    int lane = threadIdx.x & 31, wid = threadIdx.x >> 5;
    int warp_m = wid & 3, warp_n = wid >> 2;

    float acc[2][8][4];
    #pragma unroll
    for (int a = 0; a < 2; ++a)
        #pragma unroll
        for (int b = 0; b < 8; ++b)
            #pragma unroll
            for (int c = 0; c < 4; ++c) acc[a][b][c] = 0.f;

    if (bx < 768) {
        // ---------------- QKV tile ----------------
        int z = bx >> 8, r = bx & 255;
        int n0 = (r & 3) * 128, m0 = (r >> 2) * 128;
        const float* bias = (z == 0) ? bq : ((z == 1) ? bk : bv);
        float* out = (z == 0) ? g_Q : ((z == 1) ? g_K : g_V);

        hmma_loop(dynsmem,
            g_hf16 + (size_t)m0 * DD,
            g_Wf16 + (size_t)z*(DD*DD) + (size_t)n0 * DD, acc);

        int row0 = m0 + warp_m*32 + (lane >> 2);
        int col0 = n0 + warp_n*64 + (lane & 3)*2;
        #pragma unroll
        for (int mf = 0; mf < 2; ++mf) {
            #pragma unroll
            for (int jf = 0; jf < 8; ++jf) {
                int cc = col0 + jf*8;
                float2 b2 = *(const float2*)(bias + cc);
                float2 o0, o1;
                o0.x = acc[mf][jf][0] + b2.x; o0.y = acc[mf][jf][1] + b2.y;
                o1.x = acc[mf][jf][2] + b2.x; o1.y = acc[mf][jf][3] + b2.y;
                *(float2*)(out + (size_t)(row0 + mf*16    )*DD + cc) = o0;
                *(float2*)(out + (size_t)(row0 + mf*16 + 8)*DD + cc) = o1;
            }
        }
    } else {
        // ---------------- mask tile ----------------
        int e = bx - 768;
        int b = e / 36;
        int t = e % 36, bi = 0;
        while (t >= 8 - bi) { t -= 8 - bi; ++bi; }
        int bj = bi + t;
        int i0 = bi * 128, j0 = bj * 128;
        bool mirror = (bi != bj);

        hmma_loop(dynsmem,
            g_hf16 + (size_t)(b*LQ + i0) * DD,
            g_hf16 + (size_t)(b*LQ + j0) * DD, acc);

        const float* seg = segments + (size_t)b * LQ * 2;
        int   gi[4], rid[4];
        float ni[4], si[4], ei[4], li[4];
        #pragma unroll
        for (int u = 0; u < 4; ++u) {
            int r = i0 + warp_m*32 + (lane >> 2) + (u >> 1)*16 + (u & 1)*8;
            gi[u] = r; rid[u] = b*LQ + r;
            ni[u] = g_invn[rid[u]];
            float cc = seg[r*2], ll = seg[r*2+1];
            si[u] = cc - ll*0.5f; ei[u] = cc + ll*0.5f; li[u] = ll;
        }

        #pragma unroll
        for (int jf = 0; jf < 8; ++jf) {
            #pragma unroll
            for (int c2 = 0; c2 < 2; ++c2) {
                int gj = j0 + warp_n*64 + jf*8 + (lane & 3)*2 + c2;
                float nj = g_invn[b*LQ + gj];
                float cj = seg[gj*2], lj = seg[gj*2+1];
                float sj = cj - lj*0.5f, ej = cj + lj*0.5f;
                #pragma unroll
                for (int u = 0; u < 4; ++u) {
                    float cosv = acc[u >> 1][jf][(u & 1)*2 + c2] * ni[u] * nj;
                    if (fabsf(cosv - 0.2f) < 2e-3f) {
                        // exact fp32 recheck (rare)
                        const float* hp = query + (size_t)gi[u]*(BZ*DD) + (size_t)b*DD;
                        const float* hq = query + (size_t)gj   *(BZ*DD) + (size_t)b*DD;
                        float d = 0.f;
                        for (int k = 0; k < DD; ++k) d += hp[k] * hq[k];
                        cosv = d * ni[u] * nj;
                    }
                    float inter = fmaxf(fminf(ei[u], ej) - fmaxf(si[u], sj), 0.f);
                    float uni   = (li[u] + lj) - inter;
                    float iou   = inter / uni;
                    bool valid = ((iou <= 0.2f) || (gi[u] == gj)) && (cosv > 0.2f);
                    if (valid) {
                        int p = atomicAdd(&g_cnt[rid[u]], 1);
                        g_idx[((size_t)rid[u] << 10) + p] = gj;
                        if (mirror) {
                            int rj = b*LQ + gj;
                            int p2 = atomicAdd(&g_cnt[rj], 1);
                            g_idx[((size_t)rj << 10) + p2] = gi[u];
                        }
                    }
                }
            }
        }
    }
}

// ---------------------------------------------------------------------------
// Kernel 3: sparse masked attention + residual (c==1 fast path)
// ---------------------------------------------------------------------------
__global__ void __launch_bounds__(256) sattn_kernel(
    const float* __restrict__ query, float* __restrict__ out)
{
    __shared__ float sc[NH][LQ];

    int row = blockIdx.x;
    int b = row >> 10, i = row & 1023;
    int c = g_cnt[row];
    const int* idx = g_idx + ((size_t)row << 10);

    if (c == 1) {
        int j = idx[0];
        int t = threadIdx.x;
        const float* Vr = g_V + (size_t)(b*LQ + j) * DD;
        size_t off = (size_t)i*(BZ*DD) + (size_t)b*DD + t*2;
        float2 v = *(const float2*)(Vr + t*2);
        float2 r = *(const float2*)(query + off);
        float2 o; o.x = v.x + r.x; o.y = v.y + r.y;
        *(float2*)(out + off) = o;
        return;
    }

    int h = threadIdx.x >> 5, lane = threadIdx.x & 31;
    const float* Qr = g_Q + (size_t)row * DD + h*DH;
    float2 q = *(const float2*)(Qr + lane*2);

    for (int t = 0; t < c; ++t) {
        int j = idx[t];
        const float* Kr = g_K + (size_t)(b*LQ + j) * DD + h*DH;
        float2 k = *(const float2*)(Kr + lane*2);
        float s = q.x*k.x + q.y*k.y;
        #pragma unroll
        for (int o = 16; o > 0; o >>= 1) s += __shfl_xor_sync(0xffffffffu, s, o);
        if (lane == 0) sc[h][t] = s * 0.125f;
    }
    __syncwarp();

    float m = -1e30f;
    for (int t = lane; t < c; t += 32) m = fmaxf(m, sc[h][t]);
    #pragma unroll
    for (int o = 16; o > 0; o >>= 1) m = fmaxf(m, __shfl_xor_sync(0xffffffffu, m, o));
    float l = 0.f;
    for (int t = lane; t < c; t += 32) {
        float p = expf(sc[h][t] - m);
        sc[h][t] = p;
        l += p;
    }
    #pragma unroll
    for (int o = 16; o > 0; o >>= 1) l += __shfl_xor_sync(0xffffffffu, l, o);
    __syncwarp();

    float o0 = 0.f, o1 = 0.f;
    for (int t = 0; t < c; ++t) {
        int j = idx[t];
        float p = sc[h][t];
        const float* Vr = g_V + (size_t)(b*LQ + j) * DD + h*DH;
        float2 v = *(const float2*)(Vr + lane*2);
        o0 += p * v.x;
        o1 += p * v.y;
    }
    float invl = 1.f / l;

    size_t off = (size_t)i*(BZ*DD) + (size_t)b*DD + h*DH + lane*2;
    float2 rv = *(const float2*)(query + off);
    float2 ov;
    ov.x = o0*invl + rv.x;
    ov.y = o1*invl + rv.y;
    *(float2*)(out + off) = ov;
}

// ---------------------------------------------------------------------------
extern "C" void kernel_launch(void* const* d_in, const int* in_sizes, int n_in,
                              void* d_out, int out_size)
{
    const float* query    = (const float*)d_in[0];
    const float* segments = (const float*)d_in[1];
    const float* Wq = (const float*)d_in[2];
    const float* bq = (const float*)d_in[3];
    const float* Wk = (const float*)d_in[4];
    const float* bk = (const float*)d_in[5];
    const float* Wv = (const float*)d_in[6];
    const float* bv = (const float*)d_in[7];
    float* out = (float*)d_out;

    cudaFuncSetAttribute(fused_gemm_kernel, cudaFuncAttributeMaxDynamicSharedMemorySize, SMEM_PIPE);

    prep_kernel      <<<1792, 256>>>(query, Wq, Wk, Wv);
    fused_gemm_kernel<<<1056, 256, SMEM_PIPE>>>(query, segments, bq, bk, bv);
    sattn_kernel     <<<MTOT, 256>>>(query, out);
}